// round 9
// baseline (speedup 1.0000x reference)
#include <cuda_runtime.h>
#include <cuda_bf16.h>
#include <math.h>
#include <stdint.h>

#define L6 6
#define BB 32
#define QQ 900
#define DD 256
#define MM (BB*QQ)                 // 28800 tokens per level
#define MD ((size_t)MM*(size_t)DD)

// ---------------- scratch (device globals; allocation-free) ----------------
__device__ __nv_bfloat16 g_ah[(size_t)L6*MM*DD];   // hs split hi
__device__ __nv_bfloat16 g_al[(size_t)L6*MM*DD];   // hs split lo
__device__ __nv_bfloat16 g_x1h[(size_t)L6*MM*DD];
__device__ __nv_bfloat16 g_x1l[(size_t)L6*MM*DD];
__device__ __nv_bfloat16 g_y1h[(size_t)L6*MM*DD];
__device__ __nv_bfloat16 g_y1l[(size_t)L6*MM*DD];
// transposed weights bf16 hi/lo: [widx][L][N=256][K=256]; widx: 0=cls_w1 1=reg_w1 2=cls_w2 3=reg_w2
__device__ __nv_bfloat16 g_wb_hi[(size_t)4*L6*DD*DD];
__device__ __nv_bfloat16 g_wb_lo[(size_t)4*L6*DD*DD];

// ---------------- helpers ----------------
__device__ __forceinline__ uint32_t smem_u32(const void* p) {
    uint32_t a;
    asm("{ .reg .u64 t; cvta.to.shared.u64 t, %1; cvt.u32.u64 %0, t; }" : "=r"(a) : "l"(p));
    return a;
}
#define CP_ASYNC16(dst, src) \
    asm volatile("cp.async.cg.shared.global [%0], [%1], 16;" :: "r"(dst), "l"(src))
#define CP_COMMIT() asm volatile("cp.async.commit_group;" ::: "memory")
#define CP_WAIT(n)  asm volatile("cp.async.wait_group %0;" :: "n"(n) : "memory")

#define LDSM4(r, addr) \
    asm volatile("ldmatrix.sync.aligned.m8n8.x4.shared.b16 {%0,%1,%2,%3}, [%4];" \
        : "=r"((r)[0]), "=r"((r)[1]), "=r"((r)[2]), "=r"((r)[3]) : "r"(addr))

__device__ __forceinline__ uint32_t pack_hi2(float x, float y, uint32_t& lo) {
    __nv_bfloat16 hx = __float2bfloat16(x), hy = __float2bfloat16(y);
    __nv_bfloat16 lx = __float2bfloat16(x - __bfloat162float(hx));
    __nv_bfloat16 ly = __float2bfloat16(y - __bfloat162float(hy));
    __nv_bfloat162 h(hx, hy), l2(lx, ly);
    lo = *reinterpret_cast<uint32_t*>(&l2);
    return *reinterpret_cast<uint32_t*>(&h);
}

__device__ __forceinline__ void mma16816(float* c, const uint32_t a[4],
                                         uint32_t b0, uint32_t b1) {
    asm volatile(
        "mma.sync.aligned.m16n8k16.row.col.f32.bf16.bf16.f32 "
        "{%0,%1,%2,%3}, {%4,%5,%6,%7}, {%8,%9}, {%0,%1,%2,%3};"
        : "+f"(c[0]), "+f"(c[1]), "+f"(c[2]), "+f"(c[3])
        : "r"(a[0]), "r"(a[1]), "r"(a[2]), "r"(a[3]), "r"(b0), "r"(b1));
}

// ---------------- pre-pass: hs fp32 -> hi/lo bf16 ----------------
__global__ __launch_bounds__(512)
void split_hs_kernel(const float* __restrict__ hs) {
    const size_t idx = (size_t)blockIdx.x * blockDim.x + threadIdx.x;  // float4 index
    const float4 f = ((const float4*)hs)[idx];
    uint32_t lo0, lo1;
    const uint32_t hi0 = pack_hi2(f.x, f.y, lo0);
    const uint32_t hi1 = pack_hi2(f.z, f.w, lo1);
    ((uint2*)g_ah)[idx] = make_uint2(hi0, hi1);
    ((uint2*)g_al)[idx] = make_uint2(lo0, lo1);
}

// ---------------- weight transpose + bf16 hi/lo split ----------------
__global__ void transpose_weights_kernel(const float* __restrict__ w0, const float* __restrict__ w1,
                                         const float* __restrict__ w2, const float* __restrict__ w3)
{
    __shared__ float sT[32][33];
    const float* srcs[4] = {w0, w1, w2, w3};
    const int z = blockIdx.z;
    const int mat = z / L6, l = z - mat * L6;
    const int k0 = blockIdx.y * 32, n0 = blockIdx.x * 32;
    const float* W = srcs[mat] + (size_t)l * DD * DD;   // [K,N] row-major
    sT[threadIdx.y][threadIdx.x] = W[(size_t)(k0 + threadIdx.y) * DD + n0 + threadIdx.x];
    __syncthreads();
    float v = sT[threadIdx.x][threadIdx.y];             // = W[k0+tx][n0+ty]
    __nv_bfloat16 hi = __float2bfloat16(v);
    __nv_bfloat16 lo = __float2bfloat16(v - __bfloat162float(hi));
    size_t o = (((size_t)mat * L6 + l) * DD + (n0 + threadIdx.y)) * DD + k0 + threadIdx.x;
    g_wb_hi[o] = hi;
    g_wb_lo[o] = lo;
}

// ---------------- HMMA GEMM stage (512 threads, cp.async + ldmatrix, fused head) ----------------
#define LDA 80
#define A_COMP 10240                // 128 rows * 80 B
#define B_COMP 20480                // 256 rows * 80 B
#define STAGE_BYTES (2*A_COMP + 2*B_COMP)   // 61440

#define OFF_BIAS   0
#define OFF_GAMMA  1024
#define OFF_BETA   2048
#define OFF_S1     3072      // 4*128*4 = 2048
#define OFF_S2     5120
#define OFF_W3     7168      // 256*12*4 = 12288
#define OFF_PSUM   19456     // 4*128*12*4 = 24576
#define OFF_TILES  44032
#define SMEM_TOTAL (OFF_TILES + 2*STAGE_BYTES)   // 166912

template<int STAGE>
__global__ __launch_bounds__(512, 1)
void gemm_stage_kernel(const float* __restrict__ bc, const float* __restrict__ gc,
                       const float* __restrict__ betac, const float* __restrict__ br,
                       const float* __restrict__ cw3, const float* __restrict__ cb3,
                       const float* __restrict__ rw3, const float* __restrict__ rb3,
                       const float* __restrict__ init_ref, const float* __restrict__ inter_ref,
                       float* __restrict__ out)
{
    extern __shared__ char smem[];
    float* biasS  = (float*)(smem + OFF_BIAS);
    float* gammaS = (float*)(smem + OFF_GAMMA);
    float* betaS  = (float*)(smem + OFF_BETA);
    float* s1buf  = (float*)(smem + OFF_S1);
    float* s2buf  = (float*)(smem + OFF_S2);
    float* W3s    = (float*)(smem + OFF_W3);     // [256][12]
    float* psum   = (float*)(smem + OFF_PSUM);   // [4][128][12]
    char*  tiles  = smem + OFF_TILES;
    const uint32_t tiles_s = smem_u32(tiles);

    const int t = threadIdx.x, lane = t & 31, wid = t >> 5;
    const int wm = wid & 3, wn = wid >> 2;       // warp tile: 32 rows x 64 cols
    const int l = blockIdx.z, path = blockIdx.y, m0 = blockIdx.x * 128;

    const int widx = STAGE * 2 + path;
    const __nv_bfloat16* Bh_g = g_wb_hi + ((size_t)widx * L6 + l) * DD * DD;
    const __nv_bfloat16* Bl_g = g_wb_lo + ((size_t)widx * L6 + l) * DD * DD;
    const __nv_bfloat16* Agh, * Agl;
    if (STAGE == 0) {
        Agh = g_ah + (size_t)l * MD + (size_t)m0 * DD;
        Agl = g_al + (size_t)l * MD + (size_t)m0 * DD;
    } else {
        Agh = (path ? g_y1h : g_x1h) + (size_t)l * MD + (size_t)m0 * DD;
        Agl = (path ? g_y1l : g_x1l) + (size_t)l * MD + (size_t)m0 * DD;
    }

    // ---- parameter loads ----
    if (t < 256) {
        biasS[t] = ((path ? br : bc) + l * DD)[t];
        if (path == 0) { gammaS[t] = gc[l * DD + t]; betaS[t] = betac[l * DD + t]; }
    }
    if (STAGE == 1) {
        const float* w3g = (path ? rw3 : cw3) + l * 2560;
        for (int idx = t; idx < 2560; idx += 512) {
            const int k = idx / 10, nc = idx - k * 10;
            W3s[k * 12 + nc] = w3g[idx];
        }
    }

    // ---- cp.async chunk loader ----
    auto load_chunk = [&](int kt, int buf) {
        const int kc = kt * 32;
        const uint32_t base = tiles_s + buf * STAGE_BYTES;
        {
            const int row = t >> 2, c = t & 3;
            const uint32_t d = base + row * LDA + c * 16;
            CP_ASYNC16(d,           Agh + (size_t)row * DD + kc + c * 8);
            CP_ASYNC16(d + A_COMP,  Agl + (size_t)row * DD + kc + c * 8);
        }
#pragma unroll
        for (int s = 0; s < 2; ++s) {
            const int idx = s * 512 + t, row = idx >> 2, c = idx & 3;
            const uint32_t d = base + 2 * A_COMP + row * LDA + c * 16;
            CP_ASYNC16(d,           Bh_g + (size_t)row * DD + kc + c * 8);
            CP_ASYNC16(d + B_COMP,  Bl_g + (size_t)row * DD + kc + c * 8);
        }
    };

    float acc[2][8][4];
#pragma unroll
    for (int mf = 0; mf < 2; ++mf)
#pragma unroll
        for (int nf = 0; nf < 8; ++nf)
#pragma unroll
            for (int i = 0; i < 4; ++i) acc[mf][nf][i] = 0.f;

    load_chunk(0, 0);
    CP_COMMIT();
    __syncthreads();   // params visible

    const int gr = lane >> 2, gc2 = (lane & 3) << 1;
    const uint32_t a_off = (uint32_t)(wm * 32 + (lane & 7) + ((lane >> 3) & 1) * 8) * LDA
                         + ((lane >> 4) & 1) * 16;
    const uint32_t b_off = (uint32_t)(wn * 64 + (lane & 7) + ((lane >> 4) & 1) * 8) * LDA
                         + ((lane >> 3) & 1) * 16;

#pragma unroll 1
    for (int kt = 0; kt < 8; ++kt) {
        if (kt < 7) { load_chunk(kt + 1, (kt + 1) & 1); CP_COMMIT(); CP_WAIT(1); }
        else        { CP_WAIT(0); }
        __syncthreads();
        {
            const uint32_t base = tiles_s + (kt & 1) * STAGE_BYTES;
            const uint32_t baseB = base + 2 * A_COMP;
#pragma unroll
            for (int ks = 0; ks < 2; ++ks) {
                const uint32_t kb = ks * 32;
                uint32_t ah[2][4], al[2][4];
#pragma unroll
                for (int mf = 0; mf < 2; ++mf) {
                    const uint32_t aa = base + a_off + mf * (16 * LDA) + kb;
                    LDSM4(ah[mf], aa);
                    LDSM4(al[mf], aa + A_COMP);
                }
                // process nfp groups in pairs; issue each split-term as a burst of
                // 8 independent MMAs (8 distinct accumulators) -> RAW distance 8
#pragma unroll
                for (int np2 = 0; np2 < 2; ++np2) {
                    uint32_t bh[2][4], bl[2][4];
#pragma unroll
                    for (int p = 0; p < 2; ++p) {
                        const uint32_t ba = baseB + b_off + (np2 * 2 + p) * (16 * LDA) + kb;
                        LDSM4(bh[p], ba);
                        LDSM4(bl[p], ba + B_COMP);
                    }
                    float* a00 = acc[0][4 * np2];   // acc[0][4np2 + {0,1,2,3}]
                    float* a10 = acc[1][4 * np2];
                    // term 1: hi * hi
#pragma unroll
                    for (int p = 0; p < 2; ++p) {
                        mma16816(a00 + (2 * p) * 4,     ah[0], bh[p][0], bh[p][1]);
                        mma16816(a10 + (2 * p) * 4,     ah[1], bh[p][0], bh[p][1]);
                        mma16816(a00 + (2 * p + 1) * 4, ah[0], bh[p][2], bh[p][3]);
                        mma16816(a10 + (2 * p + 1) * 4, ah[1], bh[p][2], bh[p][3]);
                    }
                    // term 2: lo * hi
#pragma unroll
                    for (int p = 0; p < 2; ++p) {
                        mma16816(a00 + (2 * p) * 4,     al[0], bh[p][0], bh[p][1]);
                        mma16816(a10 + (2 * p) * 4,     al[1], bh[p][0], bh[p][1]);
                        mma16816(a00 + (2 * p + 1) * 4, al[0], bh[p][2], bh[p][3]);
                        mma16816(a10 + (2 * p + 1) * 4, al[1], bh[p][2], bh[p][3]);
                    }
                    // term 3: hi * lo
#pragma unroll
                    for (int p = 0; p < 2; ++p) {
                        mma16816(a00 + (2 * p) * 4,     ah[0], bl[p][0], bl[p][1]);
                        mma16816(a10 + (2 * p) * 4,     ah[1], bl[p][0], bl[p][1]);
                        mma16816(a00 + (2 * p + 1) * 4, ah[0], bl[p][2], bl[p][3]);
                        mma16816(a10 + (2 * p + 1) * 4, ah[1], bl[p][2], bl[p][3]);
                    }
                }
            }
        }
        __syncthreads();
    }

    // ---------------- epilogue ----------------
#pragma unroll
    for (int nf = 0; nf < 8; ++nf) {
        const int cb = wn * 64 + nf * 8 + gc2;
        const float b0 = biasS[cb], b1 = biasS[cb + 1];
#pragma unroll
        for (int mf = 0; mf < 2; ++mf) {
            acc[mf][nf][0] += b0; acc[mf][nf][1] += b1;
            acc[mf][nf][2] += b0; acc[mf][nf][3] += b1;
        }
    }

    float mean_[2][2], rs_[2][2];
    if (path == 0) {
        float s1[2][2] = {{0.f,0.f},{0.f,0.f}}, s2[2][2] = {{0.f,0.f},{0.f,0.f}};
#pragma unroll
        for (int nf = 0; nf < 8; ++nf)
#pragma unroll
            for (int mf = 0; mf < 2; ++mf) {
                s1[mf][0] += acc[mf][nf][0] + acc[mf][nf][1];
                s2[mf][0] += acc[mf][nf][0]*acc[mf][nf][0] + acc[mf][nf][1]*acc[mf][nf][1];
                s1[mf][1] += acc[mf][nf][2] + acc[mf][nf][3];
                s2[mf][1] += acc[mf][nf][2]*acc[mf][nf][2] + acc[mf][nf][3]*acc[mf][nf][3];
            }
#pragma unroll
        for (int mf = 0; mf < 2; ++mf)
#pragma unroll
            for (int h = 0; h < 2; ++h) {
                s1[mf][h] += __shfl_xor_sync(0xffffffffu, s1[mf][h], 1);
                s1[mf][h] += __shfl_xor_sync(0xffffffffu, s1[mf][h], 2);
                s2[mf][h] += __shfl_xor_sync(0xffffffffu, s2[mf][h], 1);
                s2[mf][h] += __shfl_xor_sync(0xffffffffu, s2[mf][h], 2);
            }
        if ((lane & 3) == 0) {
#pragma unroll
            for (int mf = 0; mf < 2; ++mf)
#pragma unroll
                for (int h = 0; h < 2; ++h) {
                    const int row = wm * 32 + mf * 16 + h * 8 + gr;
                    s1buf[wn * 128 + row] = s1[mf][h];
                    s2buf[wn * 128 + row] = s2[mf][h];
                }
        }
        __syncthreads();
#pragma unroll
        for (int mf = 0; mf < 2; ++mf)
#pragma unroll
            for (int h = 0; h < 2; ++h) {
                const int row = wm * 32 + mf * 16 + h * 8 + gr;
                const float t1 = s1buf[row] + s1buf[128 + row] + s1buf[256 + row] + s1buf[384 + row];
                const float t2 = s2buf[row] + s2buf[128 + row] + s2buf[256 + row] + s2buf[384 + row];
                const float mean = t1 * (1.0f / 256.0f);
                const float var  = t2 * (1.0f / 256.0f) - mean * mean;
                mean_[mf][h] = mean;
                rs_[mf][h]   = rsqrtf(var + 1e-5f);
            }
    }

    if (STAGE == 0) {
        uint32_t* Ohi = (uint32_t*)((path ? g_y1h : g_x1h) + (size_t)l * MD + (size_t)m0 * DD);
        uint32_t* Olo = (uint32_t*)((path ? g_y1l : g_x1l) + (size_t)l * MD + (size_t)m0 * DD);
#pragma unroll
        for (int nf = 0; nf < 8; ++nf) {
            const int cb = wn * 64 + nf * 8 + gc2;
            float g0 = 1.f, g1 = 1.f, be0 = 0.f, be1 = 0.f;
            if (path == 0) { g0 = gammaS[cb]; g1 = gammaS[cb + 1]; be0 = betaS[cb]; be1 = betaS[cb + 1]; }
#pragma unroll
            for (int mf = 0; mf < 2; ++mf) {
                float y[4];
                if (path == 0) {
                    y[0] = (acc[mf][nf][0] - mean_[mf][0]) * rs_[mf][0] * g0 + be0;
                    y[1] = (acc[mf][nf][1] - mean_[mf][0]) * rs_[mf][0] * g1 + be1;
                    y[2] = (acc[mf][nf][2] - mean_[mf][1]) * rs_[mf][1] * g0 + be0;
                    y[3] = (acc[mf][nf][3] - mean_[mf][1]) * rs_[mf][1] * g1 + be1;
                } else {
                    y[0] = acc[mf][nf][0]; y[1] = acc[mf][nf][1];
                    y[2] = acc[mf][nf][2]; y[3] = acc[mf][nf][3];
                }
#pragma unroll
                for (int i = 0; i < 4; ++i) y[i] = fmaxf(y[i], 0.f);
                const int row0 = wm * 32 + mf * 16 + gr;
                uint32_t lo0, lo1;
                const uint32_t hi0 = pack_hi2(y[0], y[1], lo0);
                const uint32_t hi1 = pack_hi2(y[2], y[3], lo1);
                const size_t o0 = ((size_t)row0 * DD + cb) >> 1;
                const size_t o1 = ((size_t)(row0 + 8) * DD + cb) >> 1;
                Ohi[o0] = hi0; Olo[o0] = lo0;
                Ohi[o1] = hi1; Olo[o1] = lo1;
            }
        }
    } else {
        // ---- fused head ----
        float part[4][10];
#pragma unroll
        for (int s = 0; s < 4; ++s)
#pragma unroll
            for (int nc = 0; nc < 10; ++nc) part[s][nc] = 0.f;

#pragma unroll
        for (int nf = 0; nf < 8; ++nf) {
            const int cb = wn * 64 + nf * 8 + gc2;
            float g0 = 1.f, g1 = 1.f, be0 = 0.f, be1 = 0.f;
            if (path == 0) { g0 = gammaS[cb]; g1 = gammaS[cb + 1]; be0 = betaS[cb]; be1 = betaS[cb + 1]; }
            float y[2][4];
#pragma unroll
            for (int mf = 0; mf < 2; ++mf) {
                if (path == 0) {
                    y[mf][0] = (acc[mf][nf][0] - mean_[mf][0]) * rs_[mf][0] * g0 + be0;
                    y[mf][1] = (acc[mf][nf][1] - mean_[mf][0]) * rs_[mf][0] * g1 + be1;
                    y[mf][2] = (acc[mf][nf][2] - mean_[mf][1]) * rs_[mf][1] * g0 + be0;
                    y[mf][3] = (acc[mf][nf][3] - mean_[mf][1]) * rs_[mf][1] * g1 + be1;
                } else {
                    y[mf][0] = acc[mf][nf][0]; y[mf][1] = acc[mf][nf][1];
                    y[mf][2] = acc[mf][nf][2]; y[mf][3] = acc[mf][nf][3];
                }
#pragma unroll
                for (int i = 0; i < 4; ++i) y[mf][i] = fmaxf(y[mf][i], 0.f);
            }
            const float* w0 = &W3s[cb * 12];
            const float* w1 = &W3s[(cb + 1) * 12];
#pragma unroll
            for (int nc = 0; nc < 10; ++nc) {
                const float a0 = w0[nc], a1 = w1[nc];
#pragma unroll
                for (int mf = 0; mf < 2; ++mf) {
                    part[mf * 2 + 0][nc] = fmaf(y[mf][0], a0, fmaf(y[mf][1], a1, part[mf * 2 + 0][nc]));
                    part[mf * 2 + 1][nc] = fmaf(y[mf][2], a0, fmaf(y[mf][3], a1, part[mf * 2 + 1][nc]));
                }
            }
        }
#pragma unroll
        for (int s = 0; s < 4; ++s)
#pragma unroll
            for (int nc = 0; nc < 10; ++nc) {
                part[s][nc] += __shfl_xor_sync(0xffffffffu, part[s][nc], 1);
                part[s][nc] += __shfl_xor_sync(0xffffffffu, part[s][nc], 2);
            }
        if ((lane & 3) == 0) {
#pragma unroll
            for (int mf = 0; mf < 2; ++mf)
#pragma unroll
                for (int h = 0; h < 2; ++h) {
                    const int row = wm * 32 + mf * 16 + h * 8 + gr;
                    float* p = &psum[((size_t)wn * 128 + row) * 12];
#pragma unroll
                    for (int nc = 0; nc < 10; ++nc) p[nc] = part[mf * 2 + h][nc];
                }
        }
        __syncthreads();

        if (t < 128) {
            const int row = t;
            const int m = m0 + row;
            const int q = m >> 5, b = m & 31;
            const size_t base = (((size_t)l * BB + b) * QQ + q) * 10;
            float val[10];
            const float* b3 = (path ? rb3 : cb3) + l * 10;
#pragma unroll
            for (int nc = 0; nc < 10; ++nc)
                val[nc] = psum[row * 12 + nc] + psum[(128 + row) * 12 + nc]
                        + psum[(256 + row) * 12 + nc] + psum[(384 + row) * 12 + nc] + b3[nc];
            if (path == 0) {
#pragma unroll
                for (int nc = 0; nc < 10; ++nc) out[base + nc] = val[nc];   // cls scores
            } else {
                const float* rp = (l == 0)
                    ? (init_ref + ((size_t)b * QQ + q) * 3)
                    : (inter_ref + (((size_t)(l - 1) * BB + b) * QQ + q) * 3);
                float r[3];
#pragma unroll
                for (int i = 0; i < 3; ++i) {
                    const float x  = fminf(fmaxf(rp[i], 0.f), 1.f);
                    const float x1 = fmaxf(x, 1e-5f);
                    const float x2 = fmaxf(1.f - x, 1e-5f);
                    r[i] = logf(x1 / x2);
                }
                const float xy0 = 1.f / (1.f + expf(-(val[0] + r[0])));
                const float xy1 = 1.f / (1.f + expf(-(val[1] + r[1])));
                const float z   = 1.f / (1.f + expf(-(val[4] + r[2])));
                float* co = out + (size_t)L6 * BB * QQ * 10 + base;
                co[0] = xy0 * 102.4f - 51.2f;
                co[1] = xy1 * 102.4f - 51.2f;
                co[2] = val[2];
                co[3] = val[3];
                co[4] = z * 8.0f - 5.0f;
                co[5] = val[5]; co[6] = val[6]; co[7] = val[7]; co[8] = val[8]; co[9] = val[9];
            }
        }
    }
}

extern "C" void kernel_launch(void* const* d_in, const int* in_sizes, int n_in,
                              void* d_out, int out_size) {
    const float* hs        = (const float*)d_in[0];
    const float* init_ref  = (const float*)d_in[1];
    const float* inter_ref = (const float*)d_in[2];
    const float* cls_w1    = (const float*)d_in[3];
    const float* cls_b1    = (const float*)d_in[4];
    const float* ln1_g     = (const float*)d_in[5];
    const float* ln1_b     = (const float*)d_in[6];
    const float* cls_w2    = (const float*)d_in[7];
    const float* cls_b2    = (const float*)d_in[8];
    const float* ln2_g     = (const float*)d_in[9];
    const float* ln2_b     = (const float*)d_in[10];
    const float* cls_w3    = (const float*)d_in[11];
    const float* cls_b3    = (const float*)d_in[12];
    const float* reg_w1    = (const float*)d_in[13];
    const float* reg_b1    = (const float*)d_in[14];
    const float* reg_w2    = (const float*)d_in[15];
    const float* reg_b2    = (const float*)d_in[16];
    const float* reg_w3    = (const float*)d_in[17];
    const float* reg_b3    = (const float*)d_in[18];
    float* out = (float*)d_out;

    cudaFuncSetAttribute(gemm_stage_kernel<0>, cudaFuncAttributeMaxDynamicSharedMemorySize, SMEM_TOTAL);
    cudaFuncSetAttribute(gemm_stage_kernel<1>, cudaFuncAttributeMaxDynamicSharedMemorySize, SMEM_TOTAL);

    split_hs_kernel<<<(int)((size_t)L6 * MM * DD / 4 / 512), 512>>>(hs);
    transpose_weights_kernel<<<dim3(8, 8, 4 * L6), dim3(32, 32)>>>(cls_w1, reg_w1, cls_w2, reg_w2);

    dim3 grid(MM / 128, 2, L6);   // 225 x {cls,reg} x 6
    gemm_stage_kernel<0><<<grid, 512, SMEM_TOTAL>>>(cls_b1, ln1_g, ln1_b, reg_b1,
                                                    cls_w3, cls_b3, reg_w3, reg_b3,
                                                    init_ref, inter_ref, out);
    gemm_stage_kernel<1><<<grid, 512, SMEM_TOTAL>>>(cls_b2, ln2_g, ln2_b, reg_b2,
                                                    cls_w3, cls_b3, reg_w3, reg_b3,
                                                    init_ref, inter_ref, out);
}

// round 10
// speedup vs baseline: 1.0037x; 1.0037x over previous
#include <cuda_runtime.h>
#include <cuda_bf16.h>
#include <math.h>
#include <stdint.h>

#define L6 6
#define BB 32
#define QQ 900
#define DD 256
#define MM (BB*QQ)                 // 28800 tokens per level
#define MD ((size_t)MM*(size_t)DD)

// ---------------- scratch (device globals; allocation-free) ----------------
__device__ __nv_bfloat16 g_ah[(size_t)L6*MM*DD];   // hs split hi
__device__ __nv_bfloat16 g_al[(size_t)L6*MM*DD];   // hs split lo
__device__ __nv_bfloat16 g_x1h[(size_t)L6*MM*DD];
__device__ __nv_bfloat16 g_x1l[(size_t)L6*MM*DD];
__device__ __nv_bfloat16 g_y1h[(size_t)L6*MM*DD];
__device__ __nv_bfloat16 g_y1l[(size_t)L6*MM*DD];
// transposed weights bf16 hi/lo: [widx][L][N=256][K=256]; widx: 0=cls_w1 1=reg_w1 2=cls_w2 3=reg_w2
__device__ __nv_bfloat16 g_wb_hi[(size_t)4*L6*DD*DD];
__device__ __nv_bfloat16 g_wb_lo[(size_t)4*L6*DD*DD];

// ---------------- helpers ----------------
__device__ __forceinline__ uint32_t smem_u32(const void* p) {
    uint32_t a;
    asm("{ .reg .u64 t; cvta.to.shared.u64 t, %1; cvt.u32.u64 %0, t; }" : "=r"(a) : "l"(p));
    return a;
}
#define CP_ASYNC16(dst, src) \
    asm volatile("cp.async.cg.shared.global [%0], [%1], 16;" :: "r"(dst), "l"(src))
#define CP_COMMIT() asm volatile("cp.async.commit_group;" ::: "memory")
#define CP_WAIT(n)  asm volatile("cp.async.wait_group %0;" :: "n"(n) : "memory")

#define LDSM4(r, addr) \
    asm volatile("ldmatrix.sync.aligned.m8n8.x4.shared.b16 {%0,%1,%2,%3}, [%4];" \
        : "=r"((r)[0]), "=r"((r)[1]), "=r"((r)[2]), "=r"((r)[3]) : "r"(addr))

__device__ __forceinline__ uint32_t pack_hi2(float x, float y, uint32_t& lo) {
    __nv_bfloat16 hx = __float2bfloat16(x), hy = __float2bfloat16(y);
    __nv_bfloat16 lx = __float2bfloat16(x - __bfloat162float(hx));
    __nv_bfloat16 ly = __float2bfloat16(y - __bfloat162float(hy));
    __nv_bfloat162 h(hx, hy), l2(lx, ly);
    lo = *reinterpret_cast<uint32_t*>(&l2);
    return *reinterpret_cast<uint32_t*>(&h);
}

__device__ __forceinline__ void mma16816(float* c, const uint32_t a[4],
                                         uint32_t b0, uint32_t b1) {
    asm volatile(
        "mma.sync.aligned.m16n8k16.row.col.f32.bf16.bf16.f32 "
        "{%0,%1,%2,%3}, {%4,%5,%6,%7}, {%8,%9}, {%0,%1,%2,%3};"
        : "+f"(c[0]), "+f"(c[1]), "+f"(c[2]), "+f"(c[3])
        : "r"(a[0]), "r"(a[1]), "r"(a[2]), "r"(a[3]), "r"(b0), "r"(b1));
}

// ---------------- pre-pass: hs fp32 -> hi/lo bf16 ----------------
__global__ __launch_bounds__(512)
void split_hs_kernel(const float* __restrict__ hs) {
    const size_t idx = (size_t)blockIdx.x * blockDim.x + threadIdx.x;  // float4 index
    const float4 f = ((const float4*)hs)[idx];
    uint32_t lo0, lo1;
    const uint32_t hi0 = pack_hi2(f.x, f.y, lo0);
    const uint32_t hi1 = pack_hi2(f.z, f.w, lo1);
    ((uint2*)g_ah)[idx] = make_uint2(hi0, hi1);
    ((uint2*)g_al)[idx] = make_uint2(lo0, lo1);
}

// ---------------- weight transpose + bf16 hi/lo split ----------------
__global__ void transpose_weights_kernel(const float* __restrict__ w0, const float* __restrict__ w1,
                                         const float* __restrict__ w2, const float* __restrict__ w3)
{
    __shared__ float sT[32][33];
    const float* srcs[4] = {w0, w1, w2, w3};
    const int z = blockIdx.z;
    const int mat = z / L6, l = z - mat * L6;
    const int k0 = blockIdx.y * 32, n0 = blockIdx.x * 32;
    const float* W = srcs[mat] + (size_t)l * DD * DD;   // [K,N] row-major
    sT[threadIdx.y][threadIdx.x] = W[(size_t)(k0 + threadIdx.y) * DD + n0 + threadIdx.x];
    __syncthreads();
    float v = sT[threadIdx.x][threadIdx.y];             // = W[k0+tx][n0+ty]
    __nv_bfloat16 hi = __float2bfloat16(v);
    __nv_bfloat16 lo = __float2bfloat16(v - __bfloat162float(hi));
    size_t o = (((size_t)mat * L6 + l) * DD + (n0 + threadIdx.y)) * DD + k0 + threadIdx.x;
    g_wb_hi[o] = hi;
    g_wb_lo[o] = lo;
}

// ---------------- HMMA GEMM stage (512 threads, 3-stage cp.async pipeline) ----------------
#define LDA 80
#define A_COMP 10240                // 128 rows * 80 B
#define B_COMP 20480                // 256 rows * 80 B
#define STAGE_BYTES (2*A_COMP + 2*B_COMP)   // 61440

#define OFF_BIAS   0
#define OFF_GAMMA  1024
#define OFF_BETA   2048
#define OFF_S1     3072      // 4*128*4 = 2048
#define OFF_S2     5120
#define OFF_W3     7168      // 256*12*4 = 12288
#define OFF_TILES  19456
// psum (24576 B) aliases the tile region; tiles are dead by the epilogue.
#define SMEM_TOTAL (OFF_TILES + 3*STAGE_BYTES)   // 203776

template<int STAGE>
__global__ __launch_bounds__(512, 1)
void gemm_stage_kernel(const float* __restrict__ bc, const float* __restrict__ gc,
                       const float* __restrict__ betac, const float* __restrict__ br,
                       const float* __restrict__ cw3, const float* __restrict__ cb3,
                       const float* __restrict__ rw3, const float* __restrict__ rb3,
                       const float* __restrict__ init_ref, const float* __restrict__ inter_ref,
                       float* __restrict__ out)
{
    extern __shared__ char smem[];
    float* biasS  = (float*)(smem + OFF_BIAS);
    float* gammaS = (float*)(smem + OFF_GAMMA);
    float* betaS  = (float*)(smem + OFF_BETA);
    float* s1buf  = (float*)(smem + OFF_S1);
    float* s2buf  = (float*)(smem + OFF_S2);
    float* W3s    = (float*)(smem + OFF_W3);     // [256][12]
    char*  tiles  = smem + OFF_TILES;
    float* psum   = (float*)(smem + OFF_TILES);  // aliased: [4][128][12], used post-mainloop
    const uint32_t tiles_s = smem_u32(tiles);

    const int t = threadIdx.x, lane = t & 31, wid = t >> 5;
    const int wm = wid & 3, wn = wid >> 2;       // warp tile: 32 rows x 64 cols
    const int l = blockIdx.z, path = blockIdx.y, m0 = blockIdx.x * 128;

    const int widx = STAGE * 2 + path;
    const __nv_bfloat16* Bh_g = g_wb_hi + ((size_t)widx * L6 + l) * DD * DD;
    const __nv_bfloat16* Bl_g = g_wb_lo + ((size_t)widx * L6 + l) * DD * DD;
    const __nv_bfloat16* Agh, * Agl;
    if (STAGE == 0) {
        Agh = g_ah + (size_t)l * MD + (size_t)m0 * DD;
        Agl = g_al + (size_t)l * MD + (size_t)m0 * DD;
    } else {
        Agh = (path ? g_y1h : g_x1h) + (size_t)l * MD + (size_t)m0 * DD;
        Agl = (path ? g_y1l : g_x1l) + (size_t)l * MD + (size_t)m0 * DD;
    }

    // ---- parameter loads ----
    if (t < 256) {
        biasS[t] = ((path ? br : bc) + l * DD)[t];
        if (path == 0) { gammaS[t] = gc[l * DD + t]; betaS[t] = betac[l * DD + t]; }
    }
    if (STAGE == 1) {
        const float* w3g = (path ? rw3 : cw3) + l * 2560;
        for (int idx = t; idx < 2560; idx += 512) {
            const int k = idx / 10, nc = idx - k * 10;
            W3s[k * 12 + nc] = w3g[idx];
        }
    }

    // ---- cp.async chunk loader ----
    auto load_chunk = [&](int kt, int buf) {
        const int kc = kt * 32;
        const uint32_t base = tiles_s + buf * STAGE_BYTES;
        {
            const int row = t >> 2, c = t & 3;
            const uint32_t d = base + row * LDA + c * 16;
            CP_ASYNC16(d,           Agh + (size_t)row * DD + kc + c * 8);
            CP_ASYNC16(d + A_COMP,  Agl + (size_t)row * DD + kc + c * 8);
        }
#pragma unroll
        for (int s = 0; s < 2; ++s) {
            const int idx = s * 512 + t, row = idx >> 2, c = idx & 3;
            const uint32_t d = base + 2 * A_COMP + row * LDA + c * 16;
            CP_ASYNC16(d,           Bh_g + (size_t)row * DD + kc + c * 8);
            CP_ASYNC16(d + B_COMP,  Bl_g + (size_t)row * DD + kc + c * 8);
        }
    };

    float acc[2][8][4];
#pragma unroll
    for (int mf = 0; mf < 2; ++mf)
#pragma unroll
        for (int nf = 0; nf < 8; ++nf)
#pragma unroll
            for (int i = 0; i < 4; ++i) acc[mf][nf][i] = 0.f;

    load_chunk(0, 0); CP_COMMIT();
    load_chunk(1, 1); CP_COMMIT();

    const int gr = lane >> 2, gc2 = (lane & 3) << 1;
    const uint32_t a_off = (uint32_t)(wm * 32 + (lane & 7) + ((lane >> 3) & 1) * 8) * LDA
                         + ((lane >> 4) & 1) * 16;
    const uint32_t b_off = (uint32_t)(wn * 64 + (lane & 7) + ((lane >> 4) & 1) * 8) * LDA
                         + ((lane >> 3) & 1) * 16;

    int buf = 0;   // buf == kt % 3
#pragma unroll 1
    for (int kt = 0; kt < 8; ++kt) {
        if (kt < 7) CP_WAIT(1); else CP_WAIT(0);
        // Single barrier: publishes buffer kt AND proves all warps finished kt-1,
        // so loading into (kt+2)%3 == (kt-1)%3 below is race-free.
        __syncthreads();
        if (kt < 6) {
            int nbuf = buf + 2; if (nbuf >= 3) nbuf -= 3;
            load_chunk(kt + 2, nbuf);
            CP_COMMIT();
        }
        {
            const uint32_t base = tiles_s + buf * STAGE_BYTES;
            const uint32_t baseB = base + 2 * A_COMP;
#pragma unroll
            for (int ks = 0; ks < 2; ++ks) {
                const uint32_t kb = ks * 32;
                uint32_t ah[2][4], al[2][4];
#pragma unroll
                for (int mf = 0; mf < 2; ++mf) {
                    const uint32_t aa = base + a_off + mf * (16 * LDA) + kb;
                    LDSM4(ah[mf], aa);
                    LDSM4(al[mf], aa + A_COMP);
                }
#pragma unroll
                for (int np2 = 0; np2 < 2; ++np2) {
                    uint32_t bh[2][4], bl[2][4];
#pragma unroll
                    for (int p = 0; p < 2; ++p) {
                        const uint32_t ba = baseB + b_off + (np2 * 2 + p) * (16 * LDA) + kb;
                        LDSM4(bh[p], ba);
                        LDSM4(bl[p], ba + B_COMP);
                    }
                    float* a00 = acc[0][4 * np2];
                    float* a10 = acc[1][4 * np2];
#pragma unroll
                    for (int p = 0; p < 2; ++p) {
                        mma16816(a00 + (2 * p) * 4,     ah[0], bh[p][0], bh[p][1]);
                        mma16816(a10 + (2 * p) * 4,     ah[1], bh[p][0], bh[p][1]);
                        mma16816(a00 + (2 * p + 1) * 4, ah[0], bh[p][2], bh[p][3]);
                        mma16816(a10 + (2 * p + 1) * 4, ah[1], bh[p][2], bh[p][3]);
                    }
#pragma unroll
                    for (int p = 0; p < 2; ++p) {
                        mma16816(a00 + (2 * p) * 4,     al[0], bh[p][0], bh[p][1]);
                        mma16816(a10 + (2 * p) * 4,     al[1], bh[p][0], bh[p][1]);
                        mma16816(a00 + (2 * p + 1) * 4, al[0], bh[p][2], bh[p][3]);
                        mma16816(a10 + (2 * p + 1) * 4, al[1], bh[p][2], bh[p][3]);
                    }
#pragma unroll
                    for (int p = 0; p < 2; ++p) {
                        mma16816(a00 + (2 * p) * 4,     ah[0], bl[p][0], bl[p][1]);
                        mma16816(a10 + (2 * p) * 4,     ah[1], bl[p][0], bl[p][1]);
                        mma16816(a00 + (2 * p + 1) * 4, ah[0], bl[p][2], bl[p][3]);
                        mma16816(a10 + (2 * p + 1) * 4, ah[1], bl[p][2], bl[p][3]);
                    }
                }
            }
        }
        if (++buf == 3) buf = 0;
    }
    __syncthreads();   // tiles dead; psum (aliased) may now be written

    // ---------------- epilogue ----------------
#pragma unroll
    for (int nf = 0; nf < 8; ++nf) {
        const int cb = wn * 64 + nf * 8 + gc2;
        const float b0 = biasS[cb], b1 = biasS[cb + 1];
#pragma unroll
        for (int mf = 0; mf < 2; ++mf) {
            acc[mf][nf][0] += b0; acc[mf][nf][1] += b1;
            acc[mf][nf][2] += b0; acc[mf][nf][3] += b1;
        }
    }

    float mean_[2][2], rs_[2][2];
    if (path == 0) {
        float s1[2][2] = {{0.f,0.f},{0.f,0.f}}, s2[2][2] = {{0.f,0.f},{0.f,0.f}};
#pragma unroll
        for (int nf = 0; nf < 8; ++nf)
#pragma unroll
            for (int mf = 0; mf < 2; ++mf) {
                s1[mf][0] += acc[mf][nf][0] + acc[mf][nf][1];
                s2[mf][0] += acc[mf][nf][0]*acc[mf][nf][0] + acc[mf][nf][1]*acc[mf][nf][1];
                s1[mf][1] += acc[mf][nf][2] + acc[mf][nf][3];
                s2[mf][1] += acc[mf][nf][2]*acc[mf][nf][2] + acc[mf][nf][3]*acc[mf][nf][3];
            }
#pragma unroll
        for (int mf = 0; mf < 2; ++mf)
#pragma unroll
            for (int h = 0; h < 2; ++h) {
                s1[mf][h] += __shfl_xor_sync(0xffffffffu, s1[mf][h], 1);
                s1[mf][h] += __shfl_xor_sync(0xffffffffu, s1[mf][h], 2);
                s2[mf][h] += __shfl_xor_sync(0xffffffffu, s2[mf][h], 1);
                s2[mf][h] += __shfl_xor_sync(0xffffffffu, s2[mf][h], 2);
            }
        if ((lane & 3) == 0) {
#pragma unroll
            for (int mf = 0; mf < 2; ++mf)
#pragma unroll
                for (int h = 0; h < 2; ++h) {
                    const int row = wm * 32 + mf * 16 + h * 8 + gr;
                    s1buf[wn * 128 + row] = s1[mf][h];
                    s2buf[wn * 128 + row] = s2[mf][h];
                }
        }
        __syncthreads();
#pragma unroll
        for (int mf = 0; mf < 2; ++mf)
#pragma unroll
            for (int h = 0; h < 2; ++h) {
                const int row = wm * 32 + mf * 16 + h * 8 + gr;
                const float t1 = s1buf[row] + s1buf[128 + row] + s1buf[256 + row] + s1buf[384 + row];
                const float t2 = s2buf[row] + s2buf[128 + row] + s2buf[256 + row] + s2buf[384 + row];
                const float mean = t1 * (1.0f / 256.0f);
                const float var  = t2 * (1.0f / 256.0f) - mean * mean;
                mean_[mf][h] = mean;
                rs_[mf][h]   = rsqrtf(var + 1e-5f);
            }
    }

    if (STAGE == 0) {
        uint32_t* Ohi = (uint32_t*)((path ? g_y1h : g_x1h) + (size_t)l * MD + (size_t)m0 * DD);
        uint32_t* Olo = (uint32_t*)((path ? g_y1l : g_x1l) + (size_t)l * MD + (size_t)m0 * DD);
#pragma unroll
        for (int nf = 0; nf < 8; ++nf) {
            const int cb = wn * 64 + nf * 8 + gc2;
            float g0 = 1.f, g1 = 1.f, be0 = 0.f, be1 = 0.f;
            if (path == 0) { g0 = gammaS[cb]; g1 = gammaS[cb + 1]; be0 = betaS[cb]; be1 = betaS[cb + 1]; }
#pragma unroll
            for (int mf = 0; mf < 2; ++mf) {
                float y[4];
                if (path == 0) {
                    y[0] = (acc[mf][nf][0] - mean_[mf][0]) * rs_[mf][0] * g0 + be0;
                    y[1] = (acc[mf][nf][1] - mean_[mf][0]) * rs_[mf][0] * g1 + be1;
                    y[2] = (acc[mf][nf][2] - mean_[mf][1]) * rs_[mf][1] * g0 + be0;
                    y[3] = (acc[mf][nf][3] - mean_[mf][1]) * rs_[mf][1] * g1 + be1;
                } else {
                    y[0] = acc[mf][nf][0]; y[1] = acc[mf][nf][1];
                    y[2] = acc[mf][nf][2]; y[3] = acc[mf][nf][3];
                }
#pragma unroll
                for (int i = 0; i < 4; ++i) y[i] = fmaxf(y[i], 0.f);
                const int row0 = wm * 32 + mf * 16 + gr;
                uint32_t lo0, lo1;
                const uint32_t hi0 = pack_hi2(y[0], y[1], lo0);
                const uint32_t hi1 = pack_hi2(y[2], y[3], lo1);
                const size_t o0 = ((size_t)row0 * DD + cb) >> 1;
                const size_t o1 = ((size_t)(row0 + 8) * DD + cb) >> 1;
                Ohi[o0] = hi0; Olo[o0] = lo0;
                Ohi[o1] = hi1; Olo[o1] = lo1;
            }
        }
    } else {
        // ---- fused head ----
        float part[4][10];
#pragma unroll
        for (int s = 0; s < 4; ++s)
#pragma unroll
            for (int nc = 0; nc < 10; ++nc) part[s][nc] = 0.f;

#pragma unroll
        for (int nf = 0; nf < 8; ++nf) {
            const int cb = wn * 64 + nf * 8 + gc2;
            float g0 = 1.f, g1 = 1.f, be0 = 0.f, be1 = 0.f;
            if (path == 0) { g0 = gammaS[cb]; g1 = gammaS[cb + 1]; be0 = betaS[cb]; be1 = betaS[cb + 1]; }
            float y[2][4];
#pragma unroll
            for (int mf = 0; mf < 2; ++mf) {
                if (path == 0) {
                    y[mf][0] = (acc[mf][nf][0] - mean_[mf][0]) * rs_[mf][0] * g0 + be0;
                    y[mf][1] = (acc[mf][nf][1] - mean_[mf][0]) * rs_[mf][0] * g1 + be1;
                    y[mf][2] = (acc[mf][nf][2] - mean_[mf][1]) * rs_[mf][1] * g0 + be0;
                    y[mf][3] = (acc[mf][nf][3] - mean_[mf][1]) * rs_[mf][1] * g1 + be1;
                } else {
                    y[mf][0] = acc[mf][nf][0]; y[mf][1] = acc[mf][nf][1];
                    y[mf][2] = acc[mf][nf][2]; y[mf][3] = acc[mf][nf][3];
                }
#pragma unroll
                for (int i = 0; i < 4; ++i) y[mf][i] = fmaxf(y[mf][i], 0.f);
            }
            const float* w0 = &W3s[cb * 12];
            const float* w1 = &W3s[(cb + 1) * 12];
#pragma unroll
            for (int nc = 0; nc < 10; ++nc) {
                const float a0 = w0[nc], a1 = w1[nc];
#pragma unroll
                for (int mf = 0; mf < 2; ++mf) {
                    part[mf * 2 + 0][nc] = fmaf(y[mf][0], a0, fmaf(y[mf][1], a1, part[mf * 2 + 0][nc]));
                    part[mf * 2 + 1][nc] = fmaf(y[mf][2], a0, fmaf(y[mf][3], a1, part[mf * 2 + 1][nc]));
                }
            }
        }
#pragma unroll
        for (int s = 0; s < 4; ++s)
#pragma unroll
            for (int nc = 0; nc < 10; ++nc) {
                part[s][nc] += __shfl_xor_sync(0xffffffffu, part[s][nc], 1);
                part[s][nc] += __shfl_xor_sync(0xffffffffu, part[s][nc], 2);
            }
        if ((lane & 3) == 0) {
#pragma unroll
            for (int mf = 0; mf < 2; ++mf)
#pragma unroll
                for (int h = 0; h < 2; ++h) {
                    const int row = wm * 32 + mf * 16 + h * 8 + gr;
                    float* p = &psum[((size_t)wn * 128 + row) * 12];
#pragma unroll
                    for (int nc = 0; nc < 10; ++nc) p[nc] = part[mf * 2 + h][nc];
                }
        }
        __syncthreads();

        if (t < 128) {
            const int row = t;
            const int m = m0 + row;
            const int q = m >> 5, b = m & 31;
            const size_t base = (((size_t)l * BB + b) * QQ + q) * 10;
            float val[10];
            const float* b3 = (path ? rb3 : cb3) + l * 10;
#pragma unroll
            for (int nc = 0; nc < 10; ++nc)
                val[nc] = psum[row * 12 + nc] + psum[(128 + row) * 12 + nc]
                        + psum[(256 + row) * 12 + nc] + psum[(384 + row) * 12 + nc] + b3[nc];
            if (path == 0) {
#pragma unroll
                for (int nc = 0; nc < 10; ++nc) out[base + nc] = val[nc];   // cls scores
            } else {
                const float* rp = (l == 0)
                    ? (init_ref + ((size_t)b * QQ + q) * 3)
                    : (inter_ref + (((size_t)(l - 1) * BB + b) * QQ + q) * 3);
                float r[3];
#pragma unroll
                for (int i = 0; i < 3; ++i) {
                    const float x  = fminf(fmaxf(rp[i], 0.f), 1.f);
                    const float x1 = fmaxf(x, 1e-5f);
                    const float x2 = fmaxf(1.f - x, 1e-5f);
                    r[i] = logf(x1 / x2);
                }
                const float xy0 = 1.f / (1.f + expf(-(val[0] + r[0])));
                const float xy1 = 1.f / (1.f + expf(-(val[1] + r[1])));
                const float z   = 1.f / (1.f + expf(-(val[4] + r[2])));
                float* co = out + (size_t)L6 * BB * QQ * 10 + base;
                co[0] = xy0 * 102.4f - 51.2f;
                co[1] = xy1 * 102.4f - 51.2f;
                co[2] = val[2];
                co[3] = val[3];
                co[4] = z * 8.0f - 5.0f;
                co[5] = val[5]; co[6] = val[6]; co[7] = val[7]; co[8] = val[8]; co[9] = val[9];
            }
        }
    }
}

extern "C" void kernel_launch(void* const* d_in, const int* in_sizes, int n_in,
                              void* d_out, int out_size) {
    const float* hs        = (const float*)d_in[0];
    const float* init_ref  = (const float*)d_in[1];
    const float* inter_ref = (const float*)d_in[2];
    const float* cls_w1    = (const float*)d_in[3];
    const float* cls_b1    = (const float*)d_in[4];
    const float* ln1_g     = (const float*)d_in[5];
    const float* ln1_b     = (const float*)d_in[6];
    const float* cls_w2    = (const float*)d_in[7];
    const float* cls_b2    = (const float*)d_in[8];
    const float* ln2_g     = (const float*)d_in[9];
    const float* ln2_b     = (const float*)d_in[10];
    const float* cls_w3    = (const float*)d_in[11];
    const float* cls_b3    = (const float*)d_in[12];
    const float* reg_w1    = (const float*)d_in[13];
    const float* reg_b1    = (const float*)d_in[14];
    const float* reg_w2    = (const float*)d_in[15];
    const float* reg_b2    = (const float*)d_in[16];
    const float* reg_w3    = (const float*)d_in[17];
    const float* reg_b3    = (const float*)d_in[18];
    float* out = (float*)d_out;

    cudaFuncSetAttribute(gemm_stage_kernel<0>, cudaFuncAttributeMaxDynamicSharedMemorySize, SMEM_TOTAL);
    cudaFuncSetAttribute(gemm_stage_kernel<1>, cudaFuncAttributeMaxDynamicSharedMemorySize, SMEM_TOTAL);

    split_hs_kernel<<<(int)((size_t)L6 * MM * DD / 4 / 512), 512>>>(hs);
    transpose_weights_kernel<<<dim3(8, 8, 4 * L6), dim3(32, 32)>>>(cls_w1, reg_w1, cls_w2, reg_w2);

    dim3 grid(MM / 128, 2, L6);   // 225 x {cls,reg} x 6
    gemm_stage_kernel<0><<<grid, 512, SMEM_TOTAL>>>(cls_b1, ln1_g, ln1_b, reg_b1,
                                                    cls_w3, cls_b3, reg_w3, reg_b3,
                                                    init_ref, inter_ref, out);
    gemm_stage_kernel<1><<<grid, 512, SMEM_TOTAL>>>(cls_b2, ln2_g, ln2_b, reg_b2,
                                                    cls_w3, cls_b3, reg_w3, reg_b3,
                                                    init_ref, inter_ref, out);
}

// round 11
// speedup vs baseline: 1.2408x; 1.2362x over previous
#include <cuda_runtime.h>
#include <cuda_fp16.h>
#include <math.h>
#include <stdint.h>

#define L6 6
#define BB 32
#define QQ 900
#define DD 256
#define MM (BB*QQ)                 // 28800 tokens per level
#define MD ((size_t)MM*(size_t)DD)

// ---------------- scratch (device globals; allocation-free) ----------------
__device__ __half g_ah[(size_t)L6*MM*DD];   // hs split hi (fp16)
__device__ __half g_al[(size_t)L6*MM*DD];   // hs split lo (fp16)
__device__ __half g_x1h[(size_t)L6*MM*DD];
__device__ __half g_x1l[(size_t)L6*MM*DD];
__device__ __half g_y1h[(size_t)L6*MM*DD];
__device__ __half g_y1l[(size_t)L6*MM*DD];
// transposed weights, single fp16: [widx][L][N=256][K=256]; widx: 0=cls_w1 1=reg_w1 2=cls_w2 3=reg_w2
__device__ __half g_wb[(size_t)4*L6*DD*DD];

// ---------------- helpers ----------------
__device__ __forceinline__ uint32_t smem_u32(const void* p) {
    uint32_t a;
    asm("{ .reg .u64 t; cvta.to.shared.u64 t, %1; cvt.u32.u64 %0, t; }" : "=r"(a) : "l"(p));
    return a;
}
#define CP_ASYNC16(dst, src) \
    asm volatile("cp.async.cg.shared.global [%0], [%1], 16;" :: "r"(dst), "l"(src))
#define CP_COMMIT() asm volatile("cp.async.commit_group;" ::: "memory")
#define CP_WAIT(n)  asm volatile("cp.async.wait_group %0;" :: "n"(n) : "memory")

#define LDSM4(r, addr) \
    asm volatile("ldmatrix.sync.aligned.m8n8.x4.shared.b16 {%0,%1,%2,%3}, [%4];" \
        : "=r"((r)[0]), "=r"((r)[1]), "=r"((r)[2]), "=r"((r)[3]) : "r"(addr))

__device__ __forceinline__ uint32_t pack_hi2_f16(float x, float y, uint32_t& lo) {
    __half hx = __float2half(x), hy = __float2half(y);
    __half lx = __float2half(x - __half2float(hx));
    __half ly = __float2half(y - __half2float(hy));
    __half2 h = __halves2half2(hx, hy), l2 = __halves2half2(lx, ly);
    lo = *reinterpret_cast<uint32_t*>(&l2);
    return *reinterpret_cast<uint32_t*>(&h);
}

__device__ __forceinline__ void mma16816(float* c, const uint32_t a[4],
                                         uint32_t b0, uint32_t b1) {
    asm volatile(
        "mma.sync.aligned.m16n8k16.row.col.f32.f16.f16.f32 "
        "{%0,%1,%2,%3}, {%4,%5,%6,%7}, {%8,%9}, {%0,%1,%2,%3};"
        : "+f"(c[0]), "+f"(c[1]), "+f"(c[2]), "+f"(c[3])
        : "r"(a[0]), "r"(a[1]), "r"(a[2]), "r"(a[3]), "r"(b0), "r"(b1));
}

// ---------------- pre-pass: hs fp32 -> hi/lo fp16 ----------------
__global__ __launch_bounds__(512)
void split_hs_kernel(const float* __restrict__ hs) {
    const size_t idx = (size_t)blockIdx.x * blockDim.x + threadIdx.x;  // float4 index
    const float4 f = ((const float4*)hs)[idx];
    uint32_t lo0, lo1;
    const uint32_t hi0 = pack_hi2_f16(f.x, f.y, lo0);
    const uint32_t hi1 = pack_hi2_f16(f.z, f.w, lo1);
    ((uint2*)g_ah)[idx] = make_uint2(hi0, hi1);
    ((uint2*)g_al)[idx] = make_uint2(lo0, lo1);
}

// ---------------- weight transpose + fp16 round ----------------
__global__ void transpose_weights_kernel(const float* __restrict__ w0, const float* __restrict__ w1,
                                         const float* __restrict__ w2, const float* __restrict__ w3)
{
    __shared__ float sT[32][33];
    const float* srcs[4] = {w0, w1, w2, w3};
    const int z = blockIdx.z;
    const int mat = z / L6, l = z - mat * L6;
    const int k0 = blockIdx.y * 32, n0 = blockIdx.x * 32;
    const float* W = srcs[mat] + (size_t)l * DD * DD;   // [K,N] row-major
    sT[threadIdx.y][threadIdx.x] = W[(size_t)(k0 + threadIdx.y) * DD + n0 + threadIdx.x];
    __syncthreads();
    float v = sT[threadIdx.x][threadIdx.y];             // = W[k0+tx][n0+ty]
    size_t o = (((size_t)mat * L6 + l) * DD + (n0 + threadIdx.y)) * DD + k0 + threadIdx.x;
    g_wb[o] = __float2half(v);
}

// ---------------- HMMA GEMM stage (512 threads, 3-stage cp.async, 2-term fp16) ----------------
#define LDA 80
#define A_COMP 10240                // 128 rows * 80 B
#define B_COMP 20480                // 256 rows * 80 B
#define STAGE_BYTES (2*A_COMP + B_COMP)   // 40960

#define OFF_BIAS   0
#define OFF_GAMMA  1024
#define OFF_BETA   2048
#define OFF_S1     3072      // 4*128*4 = 2048
#define OFF_S2     5120
#define OFF_W3     7168      // 256*12*4 = 12288
#define OFF_TILES  19456
// psum (24576 B) aliases the tile region; tiles are dead by the epilogue.
#define SMEM_TOTAL (OFF_TILES + 3*STAGE_BYTES)   // 142336

template<int STAGE>
__global__ __launch_bounds__(512, 1)
void gemm_stage_kernel(const float* __restrict__ bc, const float* __restrict__ gc,
                       const float* __restrict__ betac, const float* __restrict__ br,
                       const float* __restrict__ cw3, const float* __restrict__ cb3,
                       const float* __restrict__ rw3, const float* __restrict__ rb3,
                       const float* __restrict__ init_ref, const float* __restrict__ inter_ref,
                       float* __restrict__ out)
{
    extern __shared__ char smem[];
    float* biasS  = (float*)(smem + OFF_BIAS);
    float* gammaS = (float*)(smem + OFF_GAMMA);
    float* betaS  = (float*)(smem + OFF_BETA);
    float* s1buf  = (float*)(smem + OFF_S1);
    float* s2buf  = (float*)(smem + OFF_S2);
    float* W3s    = (float*)(smem + OFF_W3);     // [256][12]
    char*  tiles  = smem + OFF_TILES;
    float* psum   = (float*)(smem + OFF_TILES);  // aliased: [4][128][12], post-mainloop only
    const uint32_t tiles_s = smem_u32(tiles);

    const int t = threadIdx.x, lane = t & 31, wid = t >> 5;
    const int wm = wid & 3, wn = wid >> 2;       // warp tile: 32 rows x 64 cols
    const int l = blockIdx.z, path = blockIdx.y, m0 = blockIdx.x * 128;

    const int widx = STAGE * 2 + path;
    const __half* Bg = g_wb + ((size_t)widx * L6 + l) * DD * DD;
    const __half* Agh, * Agl;
    if (STAGE == 0) {
        Agh = g_ah + (size_t)l * MD + (size_t)m0 * DD;
        Agl = g_al + (size_t)l * MD + (size_t)m0 * DD;
    } else {
        Agh = (path ? g_y1h : g_x1h) + (size_t)l * MD + (size_t)m0 * DD;
        Agl = (path ? g_y1l : g_x1l) + (size_t)l * MD + (size_t)m0 * DD;
    }

    // ---- parameter loads ----
    if (t < 256) {
        biasS[t] = ((path ? br : bc) + l * DD)[t];
        if (path == 0) { gammaS[t] = gc[l * DD + t]; betaS[t] = betac[l * DD + t]; }
    }
    if (STAGE == 1) {
        const float* w3g = (path ? rw3 : cw3) + l * 2560;
        for (int idx = t; idx < 2560; idx += 512) {
            const int k = idx / 10, nc = idx - k * 10;
            W3s[k * 12 + nc] = w3g[idx];
        }
    }

    // ---- cp.async chunk loader ----
    auto load_chunk = [&](int kt, int buf) {
        const int kc = kt * 32;
        const uint32_t base = tiles_s + buf * STAGE_BYTES;
        {
            const int row = t >> 2, c = t & 3;
            const uint32_t d = base + row * LDA + c * 16;
            CP_ASYNC16(d,           Agh + (size_t)row * DD + kc + c * 8);
            CP_ASYNC16(d + A_COMP,  Agl + (size_t)row * DD + kc + c * 8);
        }
#pragma unroll
        for (int s = 0; s < 2; ++s) {
            const int idx = s * 512 + t, row = idx >> 2, c = idx & 3;
            const uint32_t d = base + 2 * A_COMP + row * LDA + c * 16;
            CP_ASYNC16(d, Bg + (size_t)row * DD + kc + c * 8);
        }
    };

    float acc[2][8][4];
#pragma unroll
    for (int mf = 0; mf < 2; ++mf)
#pragma unroll
        for (int nf = 0; nf < 8; ++nf)
#pragma unroll
            for (int i = 0; i < 4; ++i) acc[mf][nf][i] = 0.f;

    load_chunk(0, 0); CP_COMMIT();
    load_chunk(1, 1); CP_COMMIT();

    const int gr = lane >> 2, gc2 = (lane & 3) << 1;
    const uint32_t a_off = (uint32_t)(wm * 32 + (lane & 7) + ((lane >> 3) & 1) * 8) * LDA
                         + ((lane >> 4) & 1) * 16;
    const uint32_t b_off = (uint32_t)(wn * 64 + (lane & 7) + ((lane >> 4) & 1) * 8) * LDA
                         + ((lane >> 3) & 1) * 16;

    int buf = 0;   // buf == kt % 3
#pragma unroll 1
    for (int kt = 0; kt < 8; ++kt) {
        if (kt < 7) CP_WAIT(1); else CP_WAIT(0);
        __syncthreads();   // publishes buffer kt; proves kt-1 consumed
        if (kt < 6) {
            int nbuf = buf + 2; if (nbuf >= 3) nbuf -= 3;
            load_chunk(kt + 2, nbuf);
            CP_COMMIT();
        }
        {
            const uint32_t base = tiles_s + buf * STAGE_BYTES;
            const uint32_t baseB = base + 2 * A_COMP;
#pragma unroll
            for (int ks = 0; ks < 2; ++ks) {
                const uint32_t kb = ks * 32;
                uint32_t ah[2][4], al[2][4];
#pragma unroll
                for (int mf = 0; mf < 2; ++mf) {
                    const uint32_t aa = base + a_off + mf * (16 * LDA) + kb;
                    LDSM4(ah[mf], aa);
                    LDSM4(al[mf], aa + A_COMP);
                }
#pragma unroll
                for (int np2 = 0; np2 < 2; ++np2) {
                    uint32_t bh[2][4];
#pragma unroll
                    for (int p = 0; p < 2; ++p) {
                        const uint32_t ba = baseB + b_off + (np2 * 2 + p) * (16 * LDA) + kb;
                        LDSM4(bh[p], ba);
                    }
                    float* a00 = acc[0][4 * np2];
                    float* a10 = acc[1][4 * np2];
                    // term 1: Ah * W (burst of 8 independent accumulators)
#pragma unroll
                    for (int p = 0; p < 2; ++p) {
                        mma16816(a00 + (2 * p) * 4,     ah[0], bh[p][0], bh[p][1]);
                        mma16816(a10 + (2 * p) * 4,     ah[1], bh[p][0], bh[p][1]);
                        mma16816(a00 + (2 * p + 1) * 4, ah[0], bh[p][2], bh[p][3]);
                        mma16816(a10 + (2 * p + 1) * 4, ah[1], bh[p][2], bh[p][3]);
                    }
                    // term 2: Al * W
#pragma unroll
                    for (int p = 0; p < 2; ++p) {
                        mma16816(a00 + (2 * p) * 4,     al[0], bh[p][0], bh[p][1]);
                        mma16816(a10 + (2 * p) * 4,     al[1], bh[p][0], bh[p][1]);
                        mma16816(a00 + (2 * p + 1) * 4, al[0], bh[p][2], bh[p][3]);
                        mma16816(a10 + (2 * p + 1) * 4, al[1], bh[p][2], bh[p][3]);
                    }
                }
            }
        }
        if (++buf == 3) buf = 0;
    }
    __syncthreads();   // tiles dead; psum (aliased) may now be written

    // ---------------- epilogue ----------------
#pragma unroll
    for (int nf = 0; nf < 8; ++nf) {
        const int cb = wn * 64 + nf * 8 + gc2;
        const float b0 = biasS[cb], b1 = biasS[cb + 1];
#pragma unroll
        for (int mf = 0; mf < 2; ++mf) {
            acc[mf][nf][0] += b0; acc[mf][nf][1] += b1;
            acc[mf][nf][2] += b0; acc[mf][nf][3] += b1;
        }
    }

    float mean_[2][2], rs_[2][2];
    if (path == 0) {
        float s1[2][2] = {{0.f,0.f},{0.f,0.f}}, s2[2][2] = {{0.f,0.f},{0.f,0.f}};
#pragma unroll
        for (int nf = 0; nf < 8; ++nf)
#pragma unroll
            for (int mf = 0; mf < 2; ++mf) {
                s1[mf][0] += acc[mf][nf][0] + acc[mf][nf][1];
                s2[mf][0] += acc[mf][nf][0]*acc[mf][nf][0] + acc[mf][nf][1]*acc[mf][nf][1];
                s1[mf][1] += acc[mf][nf][2] + acc[mf][nf][3];
                s2[mf][1] += acc[mf][nf][2]*acc[mf][nf][2] + acc[mf][nf][3]*acc[mf][nf][3];
            }
#pragma unroll
        for (int mf = 0; mf < 2; ++mf)
#pragma unroll
            for (int h = 0; h < 2; ++h) {
                s1[mf][h] += __shfl_xor_sync(0xffffffffu, s1[mf][h], 1);
                s1[mf][h] += __shfl_xor_sync(0xffffffffu, s1[mf][h], 2);
                s2[mf][h] += __shfl_xor_sync(0xffffffffu, s2[mf][h], 1);
                s2[mf][h] += __shfl_xor_sync(0xffffffffu, s2[mf][h], 2);
            }
        if ((lane & 3) == 0) {
#pragma unroll
            for (int mf = 0; mf < 2; ++mf)
#pragma unroll
                for (int h = 0; h < 2; ++h) {
                    const int row = wm * 32 + mf * 16 + h * 8 + gr;
                    s1buf[wn * 128 + row] = s1[mf][h];
                    s2buf[wn * 128 + row] = s2[mf][h];
                }
        }
        __syncthreads();
#pragma unroll
        for (int mf = 0; mf < 2; ++mf)
#pragma unroll
            for (int h = 0; h < 2; ++h) {
                const int row = wm * 32 + mf * 16 + h * 8 + gr;
                const float t1 = s1buf[row] + s1buf[128 + row] + s1buf[256 + row] + s1buf[384 + row];
                const float t2 = s2buf[row] + s2buf[128 + row] + s2buf[256 + row] + s2buf[384 + row];
                const float mean = t1 * (1.0f / 256.0f);
                const float var  = t2 * (1.0f / 256.0f) - mean * mean;
                mean_[mf][h] = mean;
                rs_[mf][h]   = rsqrtf(var + 1e-5f);
            }
    }

    if (STAGE == 0) {
        uint32_t* Ohi = (uint32_t*)((path ? g_y1h : g_x1h) + (size_t)l * MD + (size_t)m0 * DD);
        uint32_t* Olo = (uint32_t*)((path ? g_y1l : g_x1l) + (size_t)l * MD + (size_t)m0 * DD);
#pragma unroll
        for (int nf = 0; nf < 8; ++nf) {
            const int cb = wn * 64 + nf * 8 + gc2;
            float g0 = 1.f, g1 = 1.f, be0 = 0.f, be1 = 0.f;
            if (path == 0) { g0 = gammaS[cb]; g1 = gammaS[cb + 1]; be0 = betaS[cb]; be1 = betaS[cb + 1]; }
#pragma unroll
            for (int mf = 0; mf < 2; ++mf) {
                float y[4];
                if (path == 0) {
                    y[0] = (acc[mf][nf][0] - mean_[mf][0]) * rs_[mf][0] * g0 + be0;
                    y[1] = (acc[mf][nf][1] - mean_[mf][0]) * rs_[mf][0] * g1 + be1;
                    y[2] = (acc[mf][nf][2] - mean_[mf][1]) * rs_[mf][1] * g0 + be0;
                    y[3] = (acc[mf][nf][3] - mean_[mf][1]) * rs_[mf][1] * g1 + be1;
                } else {
                    y[0] = acc[mf][nf][0]; y[1] = acc[mf][nf][1];
                    y[2] = acc[mf][nf][2]; y[3] = acc[mf][nf][3];
                }
#pragma unroll
                for (int i = 0; i < 4; ++i) y[i] = fmaxf(y[i], 0.f);
                const int row0 = wm * 32 + mf * 16 + gr;
                uint32_t lo0, lo1;
                const uint32_t hi0 = pack_hi2_f16(y[0], y[1], lo0);
                const uint32_t hi1 = pack_hi2_f16(y[2], y[3], lo1);
                const size_t o0 = ((size_t)row0 * DD + cb) >> 1;
                const size_t o1 = ((size_t)(row0 + 8) * DD + cb) >> 1;
                Ohi[o0] = hi0; Olo[o0] = lo0;
                Ohi[o1] = hi1; Olo[o1] = lo1;
            }
        }
    } else {
        // ---- fused head ----
        float part[4][10];
#pragma unroll
        for (int s = 0; s < 4; ++s)
#pragma unroll
            for (int nc = 0; nc < 10; ++nc) part[s][nc] = 0.f;

#pragma unroll
        for (int nf = 0; nf < 8; ++nf) {
            const int cb = wn * 64 + nf * 8 + gc2;
            float g0 = 1.f, g1 = 1.f, be0 = 0.f, be1 = 0.f;
            if (path == 0) { g0 = gammaS[cb]; g1 = gammaS[cb + 1]; be0 = betaS[cb]; be1 = betaS[cb + 1]; }
            float y[2][4];
#pragma unroll
            for (int mf = 0; mf < 2; ++mf) {
                if (path == 0) {
                    y[mf][0] = (acc[mf][nf][0] - mean_[mf][0]) * rs_[mf][0] * g0 + be0;
                    y[mf][1] = (acc[mf][nf][1] - mean_[mf][0]) * rs_[mf][0] * g1 + be1;
                    y[mf][2] = (acc[mf][nf][2] - mean_[mf][1]) * rs_[mf][1] * g0 + be0;
                    y[mf][3] = (acc[mf][nf][3] - mean_[mf][1]) * rs_[mf][1] * g1 + be1;
                } else {
                    y[mf][0] = acc[mf][nf][0]; y[mf][1] = acc[mf][nf][1];
                    y[mf][2] = acc[mf][nf][2]; y[mf][3] = acc[mf][nf][3];
                }
#pragma unroll
                for (int i = 0; i < 4; ++i) y[mf][i] = fmaxf(y[mf][i], 0.f);
            }
            const float* w0 = &W3s[cb * 12];
            const float* w1 = &W3s[(cb + 1) * 12];
#pragma unroll
            for (int nc = 0; nc < 10; ++nc) {
                const float a0 = w0[nc], a1 = w1[nc];
#pragma unroll
                for (int mf = 0; mf < 2; ++mf) {
                    part[mf * 2 + 0][nc] = fmaf(y[mf][0], a0, fmaf(y[mf][1], a1, part[mf * 2 + 0][nc]));
                    part[mf * 2 + 1][nc] = fmaf(y[mf][2], a0, fmaf(y[mf][3], a1, part[mf * 2 + 1][nc]));
                }
            }
        }
#pragma unroll
        for (int s = 0; s < 4; ++s)
#pragma unroll
            for (int nc = 0; nc < 10; ++nc) {
                part[s][nc] += __shfl_xor_sync(0xffffffffu, part[s][nc], 1);
                part[s][nc] += __shfl_xor_sync(0xffffffffu, part[s][nc], 2);
            }
        if ((lane & 3) == 0) {
#pragma unroll
            for (int mf = 0; mf < 2; ++mf)
#pragma unroll
                for (int h = 0; h < 2; ++h) {
                    const int row = wm * 32 + mf * 16 + h * 8 + gr;
                    float* p = &psum[((size_t)wn * 128 + row) * 12];
#pragma unroll
                    for (int nc = 0; nc < 10; ++nc) p[nc] = part[mf * 2 + h][nc];
                }
        }
        __syncthreads();

        if (t < 128) {
            const int row = t;
            const int m = m0 + row;
            const int q = m >> 5, b = m & 31;
            const size_t base = (((size_t)l * BB + b) * QQ + q) * 10;
            float val[10];
            const float* b3 = (path ? rb3 : cb3) + l * 10;
#pragma unroll
            for (int nc = 0; nc < 10; ++nc)
                val[nc] = psum[row * 12 + nc] + psum[(128 + row) * 12 + nc]
                        + psum[(256 + row) * 12 + nc] + psum[(384 + row) * 12 + nc] + b3[nc];
            if (path == 0) {
#pragma unroll
                for (int nc = 0; nc < 10; ++nc) out[base + nc] = val[nc];   // cls scores
            } else {
                const float* rp = (l == 0)
                    ? (init_ref + ((size_t)b * QQ + q) * 3)
                    : (inter_ref + (((size_t)(l - 1) * BB + b) * QQ + q) * 3);
                float r[3];
#pragma unroll
                for (int i = 0; i < 3; ++i) {
                    const float x  = fminf(fmaxf(rp[i], 0.f), 1.f);
                    const float x1 = fmaxf(x, 1e-5f);
                    const float x2 = fmaxf(1.f - x, 1e-5f);
                    r[i] = logf(x1 / x2);
                }
                const float xy0 = 1.f / (1.f + expf(-(val[0] + r[0])));
                const float xy1 = 1.f / (1.f + expf(-(val[1] + r[1])));
                const float z   = 1.f / (1.f + expf(-(val[4] + r[2])));
                float* co = out + (size_t)L6 * BB * QQ * 10 + base;
                co[0] = xy0 * 102.4f - 51.2f;
                co[1] = xy1 * 102.4f - 51.2f;
                co[2] = val[2];
                co[3] = val[3];
                co[4] = z * 8.0f - 5.0f;
                co[5] = val[5]; co[6] = val[6]; co[7] = val[7]; co[8] = val[8]; co[9] = val[9];
            }
        }
    }
}

extern "C" void kernel_launch(void* const* d_in, const int* in_sizes, int n_in,
                              void* d_out, int out_size) {
    const float* hs        = (const float*)d_in[0];
    const float* init_ref  = (const float*)d_in[1];
    const float* inter_ref = (const float*)d_in[2];
    const float* cls_w1    = (const float*)d_in[3];
    const float* cls_b1    = (const float*)d_in[4];
    const float* ln1_g     = (const float*)d_in[5];
    const float* ln1_b     = (const float*)d_in[6];
    const float* cls_w2    = (const float*)d_in[7];
    const float* cls_b2    = (const float*)d_in[8];
    const float* ln2_g     = (const float*)d_in[9];
    const float* ln2_b     = (const float*)d_in[10];
    const float* cls_w3    = (const float*)d_in[11];
    const float* cls_b3    = (const float*)d_in[12];
    const float* reg_w1    = (const float*)d_in[13];
    const float* reg_b1    = (const float*)d_in[14];
    const float* reg_w2    = (const float*)d_in[15];
    const float* reg_b2    = (const float*)d_in[16];
    const float* reg_w3    = (const float*)d_in[17];
    const float* reg_b3    = (const float*)d_in[18];
    float* out = (float*)d_out;

    cudaFuncSetAttribute(gemm_stage_kernel<0>, cudaFuncAttributeMaxDynamicSharedMemorySize, SMEM_TOTAL);
    cudaFuncSetAttribute(gemm_stage_kernel<1>, cudaFuncAttributeMaxDynamicSharedMemorySize, SMEM_TOTAL);

    split_hs_kernel<<<(int)((size_t)L6 * MM * DD / 4 / 512), 512>>>(hs);
    transpose_weights_kernel<<<dim3(8, 8, 4 * L6), dim3(32, 32)>>>(cls_w1, reg_w1, cls_w2, reg_w2);

    dim3 grid(MM / 128, 2, L6);   // 225 x {cls,reg} x 6
    gemm_stage_kernel<0><<<grid, 512, SMEM_TOTAL>>>(cls_b1, ln1_g, ln1_b, reg_b1,
                                                    cls_w3, cls_b3, reg_w3, reg_b3,
                                                    init_ref, inter_ref, out);
    gemm_stage_kernel<1><<<grid, 512, SMEM_TOTAL>>>(cls_b2, ln2_g, ln2_b, reg_b2,
                                                    cls_w3, cls_b3, reg_w3, reg_b3,
                                                    init_ref, inter_ref, out);
}

// round 12
// speedup vs baseline: 1.4689x; 1.1838x over previous
#include <cuda_runtime.h>
#include <cuda_fp16.h>
#include <math.h>
#include <stdint.h>

#define L6 6
#define BB 32
#define QQ 900
#define DD 256
#define MM (BB*QQ)                 // 28800 tokens per level
#define MD ((size_t)MM*(size_t)DD)

// ---------------- scratch (device globals; allocation-free) ----------------
__device__ __half g_ah[(size_t)L6*MM*DD];   // hs split hi (fp16)
__device__ __half g_al[(size_t)L6*MM*DD];   // hs split lo (fp16)
__device__ __half g_x1h[(size_t)L6*MM*DD];
__device__ __half g_x1l[(size_t)L6*MM*DD];
__device__ __half g_y1h[(size_t)L6*MM*DD];
__device__ __half g_y1l[(size_t)L6*MM*DD];
// transposed weights, single fp16: [widx][L][N=256][K=256]; widx: 0=cls_w1 1=reg_w1 2=cls_w2 3=reg_w2
__device__ __half g_wb[(size_t)4*L6*DD*DD];

// ---------------- helpers ----------------
__device__ __forceinline__ uint32_t smem_u32(const void* p) {
    uint32_t a;
    asm("{ .reg .u64 t; cvta.to.shared.u64 t, %1; cvt.u32.u64 %0, t; }" : "=r"(a) : "l"(p));
    return a;
}
#define CP_ASYNC16(dst, src) \
    asm volatile("cp.async.cg.shared.global [%0], [%1], 16;" :: "r"(dst), "l"(src))
#define CP_COMMIT() asm volatile("cp.async.commit_group;" ::: "memory")
#define CP_WAIT(n)  asm volatile("cp.async.wait_group %0;" :: "n"(n) : "memory")

#define LDSM4(r, addr) \
    asm volatile("ldmatrix.sync.aligned.m8n8.x4.shared.b16 {%0,%1,%2,%3}, [%4];" \
        : "=r"((r)[0]), "=r"((r)[1]), "=r"((r)[2]), "=r"((r)[3]) : "r"(addr))

__device__ __forceinline__ uint32_t pack_hi2_f16(float x, float y, uint32_t& lo) {
    __half hx = __float2half(x), hy = __float2half(y);
    __half lx = __float2half(x - __half2float(hx));
    __half ly = __float2half(y - __half2float(hy));
    __half2 h = __halves2half2(hx, hy), l2 = __halves2half2(lx, ly);
    lo = *reinterpret_cast<uint32_t*>(&l2);
    return *reinterpret_cast<uint32_t*>(&h);
}

__device__ __forceinline__ void mma16816(float* c, const uint32_t a[4],
                                         uint32_t b0, uint32_t b1) {
    asm volatile(
        "mma.sync.aligned.m16n8k16.row.col.f32.f16.f16.f32 "
        "{%0,%1,%2,%3}, {%4,%5,%6,%7}, {%8,%9}, {%0,%1,%2,%3};"
        : "+f"(c[0]), "+f"(c[1]), "+f"(c[2]), "+f"(c[3])
        : "r"(a[0]), "r"(a[1]), "r"(a[2]), "r"(a[3]), "r"(b0), "r"(b1));
}

// ---------------- pre-pass: hs fp32 -> hi/lo fp16 ----------------
__global__ __launch_bounds__(512)
void split_hs_kernel(const float* __restrict__ hs) {
    const size_t idx = (size_t)blockIdx.x * blockDim.x + threadIdx.x;  // float4 index
    const float4 f = ((const float4*)hs)[idx];
    uint32_t lo0, lo1;
    const uint32_t hi0 = pack_hi2_f16(f.x, f.y, lo0);
    const uint32_t hi1 = pack_hi2_f16(f.z, f.w, lo1);
    ((uint2*)g_ah)[idx] = make_uint2(hi0, hi1);
    ((uint2*)g_al)[idx] = make_uint2(lo0, lo1);
}

// ---------------- weight transpose + fp16 round ----------------
__global__ void transpose_weights_kernel(const float* __restrict__ w0, const float* __restrict__ w1,
                                         const float* __restrict__ w2, const float* __restrict__ w3)
{
    __shared__ float sT[32][33];
    const float* srcs[4] = {w0, w1, w2, w3};
    const int z = blockIdx.z;
    const int mat = z / L6, l = z - mat * L6;
    const int k0 = blockIdx.y * 32, n0 = blockIdx.x * 32;
    const float* W = srcs[mat] + (size_t)l * DD * DD;   // [K,N] row-major
    sT[threadIdx.y][threadIdx.x] = W[(size_t)(k0 + threadIdx.y) * DD + n0 + threadIdx.x];
    __syncthreads();
    float v = sT[threadIdx.x][threadIdx.y];             // = W[k0+tx][n0+ty]
    size_t o = (((size_t)mat * L6 + l) * DD + (n0 + threadIdx.y)) * DD + k0 + threadIdx.x;
    g_wb[o] = __float2half(v);
}

// ---------------- HMMA GEMM stage: M=64 tile, 256 thr, 2 CTAs/SM ----------------
#define LDA 80
#define A_COMP 5120                 // 64 rows * 80 B
#define B_COMP 20480                // 256 rows * 80 B
#define STAGE_BYTES (2*A_COMP + B_COMP)   // 30720

#define OFF_BIAS   0
#define OFF_GAMMA  1024
#define OFF_BETA   2048
#define OFF_S1     3072      // 4*64*4 = 1024
#define OFF_S2     5120
#define OFF_W3     7168      // 256*12*4 = 12288
#define OFF_TILES  19456
// psum (4*64*12*4 = 12288 B) aliases the tile region (dead by the epilogue).
#define SMEM_TOTAL (OFF_TILES + 3*STAGE_BYTES)   // 111616

template<int STAGE>
__global__ __launch_bounds__(256, 2)
void gemm_stage_kernel(const float* __restrict__ bc, const float* __restrict__ gc,
                       const float* __restrict__ betac, const float* __restrict__ br,
                       const float* __restrict__ cw3, const float* __restrict__ cb3,
                       const float* __restrict__ rw3, const float* __restrict__ rb3,
                       const float* __restrict__ init_ref, const float* __restrict__ inter_ref,
                       float* __restrict__ out)
{
    extern __shared__ char smem[];
    float* biasS  = (float*)(smem + OFF_BIAS);
    float* gammaS = (float*)(smem + OFF_GAMMA);
    float* betaS  = (float*)(smem + OFF_BETA);
    float* s1buf  = (float*)(smem + OFF_S1);
    float* s2buf  = (float*)(smem + OFF_S2);
    float* W3s    = (float*)(smem + OFF_W3);     // [256][12]
    char*  tiles  = smem + OFF_TILES;
    float* psum   = (float*)(smem + OFF_TILES);  // aliased: [4][64][12], post-mainloop only
    const uint32_t tiles_s = smem_u32(tiles);

    const int t = threadIdx.x, lane = t & 31, wid = t >> 5;
    const int wm = wid & 1, wn = wid >> 1;       // warp tile: 32 rows x 64 cols
    const int l = blockIdx.z, path = blockIdx.y, m0 = blockIdx.x * 64;

    const int widx = STAGE * 2 + path;
    const __half* Bg = g_wb + ((size_t)widx * L6 + l) * DD * DD;
    const __half* Agh, * Agl;
    if (STAGE == 0) {
        Agh = g_ah + (size_t)l * MD + (size_t)m0 * DD;
        Agl = g_al + (size_t)l * MD + (size_t)m0 * DD;
    } else {
        Agh = (path ? g_y1h : g_x1h) + (size_t)l * MD + (size_t)m0 * DD;
        Agl = (path ? g_y1l : g_x1l) + (size_t)l * MD + (size_t)m0 * DD;
    }

    // ---- parameter loads ----
    biasS[t] = ((path ? br : bc) + l * DD)[t];
    if (path == 0) { gammaS[t] = gc[l * DD + t]; betaS[t] = betac[l * DD + t]; }
    if (STAGE == 1) {
        const float* w3g = (path ? rw3 : cw3) + l * 2560;
        for (int idx = t; idx < 2560; idx += 256) {
            const int k = idx / 10, nc = idx - k * 10;
            W3s[k * 12 + nc] = w3g[idx];
        }
    }

    // ---- cp.async chunk loader (256 threads) ----
    auto load_chunk = [&](int kt, int buf) {
        const int kc = kt * 32;
        const uint32_t base = tiles_s + buf * STAGE_BYTES;
        {   // A: 64 rows x 4 x 16B per component
            const int row = t >> 2, c = t & 3;
            const uint32_t d = base + row * LDA + c * 16;
            CP_ASYNC16(d,           Agh + (size_t)row * DD + kc + c * 8);
            CP_ASYNC16(d + A_COMP,  Agl + (size_t)row * DD + kc + c * 8);
        }
#pragma unroll
        for (int s = 0; s < 4; ++s) {   // B: 256 rows x 4 x 16B
            const int idx = s * 256 + t, row = idx >> 2, c = idx & 3;
            const uint32_t d = base + 2 * A_COMP + row * LDA + c * 16;
            CP_ASYNC16(d, Bg + (size_t)row * DD + kc + c * 8);
        }
    };

    float acc[2][8][4];
#pragma unroll
    for (int mf = 0; mf < 2; ++mf)
#pragma unroll
        for (int nf = 0; nf < 8; ++nf)
#pragma unroll
            for (int i = 0; i < 4; ++i) acc[mf][nf][i] = 0.f;

    load_chunk(0, 0); CP_COMMIT();
    load_chunk(1, 1); CP_COMMIT();

    const int gr = lane >> 2, gc2 = (lane & 3) << 1;
    const uint32_t a_off = (uint32_t)(wm * 32 + (lane & 7) + ((lane >> 3) & 1) * 8) * LDA
                         + ((lane >> 4) & 1) * 16;
    const uint32_t b_off = (uint32_t)(wn * 64 + (lane & 7) + ((lane >> 4) & 1) * 8) * LDA
                         + ((lane >> 3) & 1) * 16;

    int buf = 0;   // buf == kt % 3
#pragma unroll 1
    for (int kt = 0; kt < 8; ++kt) {
        if (kt < 7) CP_WAIT(1); else CP_WAIT(0);
        __syncthreads();   // publishes buffer kt; proves kt-1 consumed
        if (kt < 6) {
            int nbuf = buf + 2; if (nbuf >= 3) nbuf -= 3;
            load_chunk(kt + 2, nbuf);
            CP_COMMIT();
        }
        {
            const uint32_t base = tiles_s + buf * STAGE_BYTES;
            const uint32_t baseB = base + 2 * A_COMP;
#pragma unroll
            for (int ks = 0; ks < 2; ++ks) {
                const uint32_t kb = ks * 32;
                uint32_t ah[2][4], al[2][4];
                {
                    const uint32_t aa = base + a_off + kb;
                    LDSM4(ah[0], aa);                    // mf rows 0..15
                    LDSM4(ah[1], aa + 16 * LDA);         // mf rows 16..31 — wait, warp tile is 32 rows
                    LDSM4(al[0], aa + A_COMP);
                    LDSM4(al[1], aa + A_COMP + 16 * LDA);
                }
#pragma unroll
                for (int np2 = 0; np2 < 2; ++np2) {
                    uint32_t bh[2][4];
#pragma unroll
                    for (int p = 0; p < 2; ++p) {
                        const uint32_t ba = baseB + b_off + (np2 * 2 + p) * (16 * LDA) + kb;
                        LDSM4(bh[p], ba);
                    }
                    float* a00 = acc[0][4 * np2];
                    float* a10 = acc[1][4 * np2];
                    // term 1: Ah * W (burst of 8 independent accumulators)
#pragma unroll
                    for (int p = 0; p < 2; ++p) {
                        mma16816(a00 + (2 * p) * 4,     ah[0], bh[p][0], bh[p][1]);
                        mma16816(a10 + (2 * p) * 4,     ah[1], bh[p][0], bh[p][1]);
                        mma16816(a00 + (2 * p + 1) * 4, ah[0], bh[p][2], bh[p][3]);
                        mma16816(a10 + (2 * p + 1) * 4, ah[1], bh[p][2], bh[p][3]);
                    }
                    // term 2: Al * W
#pragma unroll
                    for (int p = 0; p < 2; ++p) {
                        mma16816(a00 + (2 * p) * 4,     al[0], bh[p][0], bh[p][1]);
                        mma16816(a10 + (2 * p) * 4,     al[1], bh[p][0], bh[p][1]);
                        mma16816(a00 + (2 * p + 1) * 4, al[0], bh[p][2], bh[p][3]);
                        mma16816(a10 + (2 * p + 1) * 4, al[1], bh[p][2], bh[p][3]);
                    }
                }
            }
        }
        if (++buf == 3) buf = 0;
    }
    __syncthreads();   // tiles dead; psum (aliased) may now be written

    // ---------------- epilogue ----------------
#pragma unroll
    for (int nf = 0; nf < 8; ++nf) {
        const int cb = wn * 64 + nf * 8 + gc2;
        const float b0 = biasS[cb], b1 = biasS[cb + 1];
#pragma unroll
        for (int mf = 0; mf < 2; ++mf) {
            acc[mf][nf][0] += b0; acc[mf][nf][1] += b1;
            acc[mf][nf][2] += b0; acc[mf][nf][3] += b1;
        }
    }

    float mean_[2][2], rs_[2][2];
    if (path == 0) {
        float s1[2][2] = {{0.f,0.f},{0.f,0.f}}, s2[2][2] = {{0.f,0.f},{0.f,0.f}};
#pragma unroll
        for (int nf = 0; nf < 8; ++nf)
#pragma unroll
            for (int mf = 0; mf < 2; ++mf) {
                s1[mf][0] += acc[mf][nf][0] + acc[mf][nf][1];
                s2[mf][0] += acc[mf][nf][0]*acc[mf][nf][0] + acc[mf][nf][1]*acc[mf][nf][1];
                s1[mf][1] += acc[mf][nf][2] + acc[mf][nf][3];
                s2[mf][1] += acc[mf][nf][2]*acc[mf][nf][2] + acc[mf][nf][3]*acc[mf][nf][3];
            }
#pragma unroll
        for (int mf = 0; mf < 2; ++mf)
#pragma unroll
            for (int h = 0; h < 2; ++h) {
                s1[mf][h] += __shfl_xor_sync(0xffffffffu, s1[mf][h], 1);
                s1[mf][h] += __shfl_xor_sync(0xffffffffu, s1[mf][h], 2);
                s2[mf][h] += __shfl_xor_sync(0xffffffffu, s2[mf][h], 1);
                s2[mf][h] += __shfl_xor_sync(0xffffffffu, s2[mf][h], 2);
            }
        if ((lane & 3) == 0) {
#pragma unroll
            for (int mf = 0; mf < 2; ++mf)
#pragma unroll
                for (int h = 0; h < 2; ++h) {
                    const int row = wm * 32 + mf * 16 + h * 8 + gr;   // 0..63
                    s1buf[wn * 64 + row] = s1[mf][h];
                    s2buf[wn * 64 + row] = s2[mf][h];
                }
        }
        __syncthreads();
#pragma unroll
        for (int mf = 0; mf < 2; ++mf)
#pragma unroll
            for (int h = 0; h < 2; ++h) {
                const int row = wm * 32 + mf * 16 + h * 8 + gr;
                const float t1 = s1buf[row] + s1buf[64 + row] + s1buf[128 + row] + s1buf[192 + row];
                const float t2 = s2buf[row] + s2buf[64 + row] + s2buf[128 + row] + s2buf[192 + row];
                const float mean = t1 * (1.0f / 256.0f);
                const float var  = t2 * (1.0f / 256.0f) - mean * mean;
                mean_[mf][h] = mean;
                rs_[mf][h]   = rsqrtf(var + 1e-5f);
            }
    }

    if (STAGE == 0) {
        uint32_t* Ohi = (uint32_t*)((path ? g_y1h : g_x1h) + (size_t)l * MD + (size_t)m0 * DD);
        uint32_t* Olo = (uint32_t*)((path ? g_y1l : g_x1l) + (size_t)l * MD + (size_t)m0 * DD);
#pragma unroll
        for (int nf = 0; nf < 8; ++nf) {
            const int cb = wn * 64 + nf * 8 + gc2;
            float g0 = 1.f, g1 = 1.f, be0 = 0.f, be1 = 0.f;
            if (path == 0) { g0 = gammaS[cb]; g1 = gammaS[cb + 1]; be0 = betaS[cb]; be1 = betaS[cb + 1]; }
#pragma unroll
            for (int mf = 0; mf < 2; ++mf) {
                float y[4];
                if (path == 0) {
                    y[0] = (acc[mf][nf][0] - mean_[mf][0]) * rs_[mf][0] * g0 + be0;
                    y[1] = (acc[mf][nf][1] - mean_[mf][0]) * rs_[mf][0] * g1 + be1;
                    y[2] = (acc[mf][nf][2] - mean_[mf][1]) * rs_[mf][1] * g0 + be0;
                    y[3] = (acc[mf][nf][3] - mean_[mf][1]) * rs_[mf][1] * g1 + be1;
                } else {
                    y[0] = acc[mf][nf][0]; y[1] = acc[mf][nf][1];
                    y[2] = acc[mf][nf][2]; y[3] = acc[mf][nf][3];
                }
#pragma unroll
                for (int i = 0; i < 4; ++i) y[i] = fmaxf(y[i], 0.f);
                const int row0 = wm * 32 + mf * 16 + gr;
                uint32_t lo0, lo1;
                const uint32_t hi0 = pack_hi2_f16(y[0], y[1], lo0);
                const uint32_t hi1 = pack_hi2_f16(y[2], y[3], lo1);
                const size_t o0 = ((size_t)row0 * DD + cb) >> 1;
                const size_t o1 = ((size_t)(row0 + 8) * DD + cb) >> 1;
                Ohi[o0] = hi0; Olo[o0] = lo0;
                Ohi[o1] = hi1; Olo[o1] = lo1;
            }
        }
    } else {
        // ---- fused head ----
        float part[4][10];
#pragma unroll
        for (int s = 0; s < 4; ++s)
#pragma unroll
            for (int nc = 0; nc < 10; ++nc) part[s][nc] = 0.f;

#pragma unroll
        for (int nf = 0; nf < 8; ++nf) {
            const int cb = wn * 64 + nf * 8 + gc2;
            float g0 = 1.f, g1 = 1.f, be0 = 0.f, be1 = 0.f;
            if (path == 0) { g0 = gammaS[cb]; g1 = gammaS[cb + 1]; be0 = betaS[cb]; be1 = betaS[cb + 1]; }
            float y[2][4];
#pragma unroll
            for (int mf = 0; mf < 2; ++mf) {
                if (path == 0) {
                    y[mf][0] = (acc[mf][nf][0] - mean_[mf][0]) * rs_[mf][0] * g0 + be0;
                    y[mf][1] = (acc[mf][nf][1] - mean_[mf][0]) * rs_[mf][0] * g1 + be1;
                    y[mf][2] = (acc[mf][nf][2] - mean_[mf][1]) * rs_[mf][1] * g0 + be0;
                    y[mf][3] = (acc[mf][nf][3] - mean_[mf][1]) * rs_[mf][1] * g1 + be1;
                } else {
                    y[mf][0] = acc[mf][nf][0]; y[mf][1] = acc[mf][nf][1];
                    y[mf][2] = acc[mf][nf][2]; y[mf][3] = acc[mf][nf][3];
                }
#pragma unroll
                for (int i = 0; i < 4; ++i) y[mf][i] = fmaxf(y[mf][i], 0.f);
            }
            const float* w0 = &W3s[cb * 12];
            const float* w1 = &W3s[(cb + 1) * 12];
#pragma unroll
            for (int nc = 0; nc < 10; ++nc) {
                const float a0 = w0[nc], a1 = w1[nc];
#pragma unroll
                for (int mf = 0; mf < 2; ++mf) {
                    part[mf * 2 + 0][nc] = fmaf(y[mf][0], a0, fmaf(y[mf][1], a1, part[mf * 2 + 0][nc]));
                    part[mf * 2 + 1][nc] = fmaf(y[mf][2], a0, fmaf(y[mf][3], a1, part[mf * 2 + 1][nc]));
                }
            }
        }
#pragma unroll
        for (int s = 0; s < 4; ++s)
#pragma unroll
            for (int nc = 0; nc < 10; ++nc) {
                part[s][nc] += __shfl_xor_sync(0xffffffffu, part[s][nc], 1);
                part[s][nc] += __shfl_xor_sync(0xffffffffu, part[s][nc], 2);
            }
        if ((lane & 3) == 0) {
#pragma unroll
            for (int mf = 0; mf < 2; ++mf)
#pragma unroll
                for (int h = 0; h < 2; ++h) {
                    const int row = wm * 32 + mf * 16 + h * 8 + gr;   // 0..63
                    float* p = &psum[((size_t)wn * 64 + row) * 12];
#pragma unroll
                    for (int nc = 0; nc < 10; ++nc) p[nc] = part[mf * 2 + h][nc];
                }
        }
        __syncthreads();

        if (t < 64) {
            const int row = t;
            const int m = m0 + row;
            const int q = m >> 5, b = m & 31;
            const size_t base = (((size_t)l * BB + b) * QQ + q) * 10;
            float val[10];
            const float* b3 = (path ? rb3 : cb3) + l * 10;
#pragma unroll
            for (int nc = 0; nc < 10; ++nc)
                val[nc] = psum[row * 12 + nc] + psum[(64 + row) * 12 + nc]
                        + psum[(128 + row) * 12 + nc] + psum[(192 + row) * 12 + nc] + b3[nc];
            if (path == 0) {
#pragma unroll
                for (int nc = 0; nc < 10; ++nc) out[base + nc] = val[nc];   // cls scores
            } else {
                const float* rp = (l == 0)
                    ? (init_ref + ((size_t)b * QQ + q) * 3)
                    : (inter_ref + (((size_t)(l - 1) * BB + b) * QQ + q) * 3);
                float r[3];
#pragma unroll
                for (int i = 0; i < 3; ++i) {
                    const float x  = fminf(fmaxf(rp[i], 0.f), 1.f);
                    const float x1 = fmaxf(x, 1e-5f);
                    const float x2 = fmaxf(1.f - x, 1e-5f);
                    r[i] = logf(x1 / x2);
                }
                const float xy0 = 1.f / (1.f + expf(-(val[0] + r[0])));
                const float xy1 = 1.f / (1.f + expf(-(val[1] + r[1])));
                const float z   = 1.f / (1.f + expf(-(val[4] + r[2])));
                float* co = out + (size_t)L6 * BB * QQ * 10 + base;
                co[0] = xy0 * 102.4f - 51.2f;
                co[1] = xy1 * 102.4f - 51.2f;
                co[2] = val[2];
                co[3] = val[3];
                co[4] = z * 8.0f - 5.0f;
                co[5] = val[5]; co[6] = val[6]; co[7] = val[7]; co[8] = val[8]; co[9] = val[9];
            }
        }
    }
}

extern "C" void kernel_launch(void* const* d_in, const int* in_sizes, int n_in,
                              void* d_out, int out_size) {
    const float* hs        = (const float*)d_in[0];
    const float* init_ref  = (const float*)d_in[1];
    const float* inter_ref = (const float*)d_in[2];
    const float* cls_w1    = (const float*)d_in[3];
    const float* cls_b1    = (const float*)d_in[4];
    const float* ln1_g     = (const float*)d_in[5];
    const float* ln1_b     = (const float*)d_in[6];
    const float* cls_w2    = (const float*)d_in[7];
    const float* cls_b2    = (const float*)d_in[8];
    const float* ln2_g     = (const float*)d_in[9];
    const float* ln2_b     = (const float*)d_in[10];
    const float* cls_w3    = (const float*)d_in[11];
    const float* cls_b3    = (const float*)d_in[12];
    const float* reg_w1    = (const float*)d_in[13];
    const float* reg_b1    = (const float*)d_in[14];
    const float* reg_w2    = (const float*)d_in[15];
    const float* reg_b2    = (const float*)d_in[16];
    const float* reg_w3    = (const float*)d_in[17];
    const float* reg_b3    = (const float*)d_in[18];
    float* out = (float*)d_out;

    cudaFuncSetAttribute(gemm_stage_kernel<0>, cudaFuncAttributeMaxDynamicSharedMemorySize, SMEM_TOTAL);
    cudaFuncSetAttribute(gemm_stage_kernel<1>, cudaFuncAttributeMaxDynamicSharedMemorySize, SMEM_TOTAL);

    split_hs_kernel<<<(int)((size_t)L6 * MM * DD / 4 / 512), 512>>>(hs);
    transpose_weights_kernel<<<dim3(8, 8, 4 * L6), dim3(32, 32)>>>(cls_w1, reg_w1, cls_w2, reg_w2);

    dim3 grid(MM / 64, 2, L6);   // 450 x {cls,reg} x 6
    gemm_stage_kernel<0><<<grid, 256, SMEM_TOTAL>>>(cls_b1, ln1_g, ln1_b, reg_b1,
                                                    cls_w3, cls_b3, reg_w3, reg_b3,
                                                    init_ref, inter_ref, out);
    gemm_stage_kernel<1><<<grid, 256, SMEM_TOTAL>>>(cls_b2, ln2_g, ln2_b, reg_b2,
                                                    cls_w3, cls_b3, reg_w3, reg_b3,
                                                    init_ref, inter_ref, out);
}

// round 13
// speedup vs baseline: 2.3361x; 1.5904x over previous
#include <cuda_runtime.h>
#include <cuda_fp16.h>
#include <math.h>
#include <stdint.h>

#define L6 6
#define BB 32
#define QQ 900
#define DD 256
#define MM (BB*QQ)                 // 28800 tokens per level
#define MD ((size_t)MM*(size_t)DD)

// ---------------- scratch (device globals; allocation-free) ----------------
__device__ __half g_ah[(size_t)L6*MM*DD];          // hs rounded to fp16
// transposed weights fp16: [widx][L][N=256][K=256]; widx: 0=cls_w1 1=reg_w1 2=cls_w2 3=reg_w2
__device__ __half g_wb[(size_t)4*L6*DD*DD];

// ---------------- helpers ----------------
__device__ __forceinline__ uint32_t smem_u32(const void* p) {
    uint32_t a;
    asm("{ .reg .u64 t; cvta.to.shared.u64 t, %1; cvt.u32.u64 %0, t; }" : "=r"(a) : "l"(p));
    return a;
}
#define CP_ASYNC16(dst, src) \
    asm volatile("cp.async.cg.shared.global [%0], [%1], 16;" :: "r"(dst), "l"(src))
#define CP_COMMIT() asm volatile("cp.async.commit_group;" ::: "memory")
#define CP_WAIT(n)  asm volatile("cp.async.wait_group %0;" :: "n"(n) : "memory")

#define LDSM4(r, addr) \
    asm volatile("ldmatrix.sync.aligned.m8n8.x4.shared.b16 {%0,%1,%2,%3}, [%4];" \
        : "=r"((r)[0]), "=r"((r)[1]), "=r"((r)[2]), "=r"((r)[3]) : "r"(addr))

__device__ __forceinline__ uint32_t pack2_f16(float x, float y) {
    __half2 h = __halves2half2(__float2half(x), __float2half(y));
    return *reinterpret_cast<uint32_t*>(&h);
}

__device__ __forceinline__ void mma16816(float* c, const uint32_t a[4],
                                         uint32_t b0, uint32_t b1) {
    asm volatile(
        "mma.sync.aligned.m16n8k16.row.col.f32.f16.f16.f32 "
        "{%0,%1,%2,%3}, {%4,%5,%6,%7}, {%8,%9}, {%0,%1,%2,%3};"
        : "+f"(c[0]), "+f"(c[1]), "+f"(c[2]), "+f"(c[3])
        : "r"(a[0]), "r"(a[1]), "r"(a[2]), "r"(a[3]), "r"(b0), "r"(b1));
}

// ---------------- pre-pass: hs fp32 -> fp16 ----------------
__global__ __launch_bounds__(512)
void split_hs_kernel(const float* __restrict__ hs) {
    const size_t idx = (size_t)blockIdx.x * blockDim.x + threadIdx.x;  // float4 index
    const float4 f = ((const float4*)hs)[idx];
    ((uint2*)g_ah)[idx] = make_uint2(pack2_f16(f.x, f.y), pack2_f16(f.z, f.w));
}

// ---------------- weight transpose + fp16 round ----------------
__global__ void transpose_weights_kernel(const float* __restrict__ w0, const float* __restrict__ w1,
                                         const float* __restrict__ w2, const float* __restrict__ w3)
{
    __shared__ float sT[32][33];
    const float* srcs[4] = {w0, w1, w2, w3};
    const int z = blockIdx.z;
    const int mat = z / L6, l = z - mat * L6;
    const int k0 = blockIdx.y * 32, n0 = blockIdx.x * 32;
    const float* W = srcs[mat] + (size_t)l * DD * DD;   // [K,N] row-major
    sT[threadIdx.y][threadIdx.x] = W[(size_t)(k0 + threadIdx.y) * DD + n0 + threadIdx.x];
    __syncthreads();
    float v = sT[threadIdx.x][threadIdx.y];             // = W[k0+tx][n0+ty]
    size_t o = (((size_t)mat * L6 + l) * DD + (n0 + threadIdx.y)) * DD + k0 + threadIdx.x;
    g_wb[o] = __float2half(v);
}

// ---------------- fused 2-layer HMMA kernel (M=64 tile, 256 thr, 2 CTAs/SM) ----------------
#define LDA 80
#define A_COMP 5120                 // 64 rows * 80 B (layer-1 A chunk)
#define B_COMP 20480                // 256 rows * 80 B
#define BUF_BYTES (A_COMP + B_COMP) // 25600: [A 5120][B 20480]
#define LDA2 528                    // A2 row stride (256 halfs + 8-half pad)

#define OFF_BIAS1  0
#define OFF_GAMMA1 1024
#define OFF_BETA1  2048
#define OFF_BIAS2  3072
#define OFF_GAMMA2 4096
#define OFF_BETA2  5120
#define OFF_S1     6144
#define OFF_S2     7168
#define OFF_W3     8192      // 256*12*4 = 12288 -> ends 20480
#define OFF_A2     20480     // 64*528 = 33792 -> ends 54272
#define OFF_BUFS   54272     // 2*25600 -> ends 105472
#define SMEM_TOTAL 105472
// psum [4][64][12] (12288 B) aliases OFF_BUFS (buffers dead by final epilogue)

__global__ __launch_bounds__(256, 2)
void fused_mlp_kernel(const float* __restrict__ bc1, const float* __restrict__ gc1,
                      const float* __restrict__ bec1, const float* __restrict__ br1,
                      const float* __restrict__ bc2, const float* __restrict__ gc2,
                      const float* __restrict__ bec2, const float* __restrict__ br2,
                      const float* __restrict__ cw3, const float* __restrict__ cb3,
                      const float* __restrict__ rw3, const float* __restrict__ rb3,
                      const float* __restrict__ init_ref, const float* __restrict__ inter_ref,
                      float* __restrict__ out)
{
    extern __shared__ char smem[];
    float* bias1S  = (float*)(smem + OFF_BIAS1);
    float* gamma1S = (float*)(smem + OFF_GAMMA1);
    float* beta1S  = (float*)(smem + OFF_BETA1);
    float* bias2S  = (float*)(smem + OFF_BIAS2);
    float* gamma2S = (float*)(smem + OFF_GAMMA2);
    float* beta2S  = (float*)(smem + OFF_BETA2);
    float* s1buf   = (float*)(smem + OFF_S1);
    float* s2buf   = (float*)(smem + OFF_S2);
    float* W3s     = (float*)(smem + OFF_W3);    // [256][12]
    float* psum    = (float*)(smem + OFF_BUFS);  // aliased
    const uint32_t sb = smem_u32(smem);
    const uint32_t bufs_s = sb + OFF_BUFS;

    const int t = threadIdx.x, lane = t & 31, wid = t >> 5;
    const int wm = wid & 1, wn = wid >> 1;       // warp tile: 32 rows x 64 cols
    const int l = blockIdx.z, path = blockIdx.y, m0 = blockIdx.x * 64;

    const __half* W1g = g_wb + ((size_t)(0 * 2 + path) * L6 + l) * DD * DD;
    const __half* W2g = g_wb + ((size_t)(1 * 2 + path) * L6 + l) * DD * DD;
    const __half* Ag  = g_ah + (size_t)l * MD + (size_t)m0 * DD;

    // ---- parameter loads ----
    bias1S[t] = ((path ? br1 : bc1) + l * DD)[t];
    bias2S[t] = ((path ? br2 : bc2) + l * DD)[t];
    if (path == 0) {
        gamma1S[t] = gc1[l * DD + t]; beta1S[t] = bec1[l * DD + t];
        gamma2S[t] = gc2[l * DD + t]; beta2S[t] = bec2[l * DD + t];
    }
    {
        const float* w3g = (path ? rw3 : cw3) + l * 2560;
        for (int idx = t; idx < 2560; idx += 256) {
            const int k = idx / 10, nc = idx - k * 10;
            W3s[k * 12 + nc] = w3g[idx];
        }
    }

    // ---- loader: g in 0..15; g<8: A1+B1 chunk g; g>=8: B2 chunk g-8 ----
    auto load_g = [&](int g, int buf) {
        const uint32_t base = bufs_s + buf * BUF_BYTES;
        if (g < 8) {
            const int kc = g * 32;
            const int row = t >> 2, c = t & 3;
            CP_ASYNC16(base + row * LDA + c * 16, Ag + (size_t)row * DD + kc + c * 8);
#pragma unroll
            for (int s = 0; s < 4; ++s) {
                const int idx = s * 256 + t, r = idx >> 2, cc = idx & 3;
                CP_ASYNC16(base + A_COMP + r * LDA + cc * 16, W1g + (size_t)r * DD + kc + cc * 8);
            }
        } else {
            const int kc = (g - 8) * 32;
#pragma unroll
            for (int s = 0; s < 4; ++s) {
                const int idx = s * 256 + t, r = idx >> 2, cc = idx & 3;
                CP_ASYNC16(base + A_COMP + r * LDA + cc * 16, W2g + (size_t)r * DD + kc + cc * 8);
            }
        }
    };

    float acc[2][8][4];
#pragma unroll
    for (int mf = 0; mf < 2; ++mf)
#pragma unroll
        for (int nf = 0; nf < 8; ++nf)
#pragma unroll
            for (int i = 0; i < 4; ++i) acc[mf][nf][i] = 0.f;

    const int gr = lane >> 2, gc2v = (lane & 3) << 1;
    const uint32_t a_off = (uint32_t)(wm * 32 + (lane & 7) + ((lane >> 3) & 1) * 8) * LDA
                         + ((lane >> 4) & 1) * 16;
    const uint32_t b_off = (uint32_t)(wn * 64 + (lane & 7) + ((lane >> 4) & 1) * 8) * LDA
                         + ((lane >> 3) & 1) * 16;
    const uint32_t a2_off = sb + OFF_A2
                          + (uint32_t)(wm * 32 + (lane & 7) + ((lane >> 3) & 1) * 8) * LDA2
                          + ((lane >> 4) & 1) * 16;

    load_g(0, 0); CP_COMMIT();

    // ================= mainloop 1 (layer 1) =================
#pragma unroll 1
    for (int kt = 0; kt < 8; ++kt) {
        CP_WAIT(0);
        __syncthreads();                 // chunk kt visible; chunk kt-1 consumed by all
        load_g(kt + 1, (kt + 1) & 1);    // kt+1 <= 8
        CP_COMMIT();
        const uint32_t base  = bufs_s + (kt & 1) * BUF_BYTES;
        const uint32_t baseB = base + A_COMP;
#pragma unroll
        for (int ks = 0; ks < 2; ++ks) {
            const uint32_t kb = ks * 32;
            uint32_t ah[2][4];
            LDSM4(ah[0], base + a_off + kb);
            LDSM4(ah[1], base + a_off + 16 * LDA + kb);
#pragma unroll
            for (int np2 = 0; np2 < 2; ++np2) {
                uint32_t bh[2][4];
#pragma unroll
                for (int p = 0; p < 2; ++p)
                    LDSM4(bh[p], baseB + b_off + (np2 * 2 + p) * (16 * LDA) + kb);
                float* a00 = acc[0][4 * np2];
                float* a10 = acc[1][4 * np2];
#pragma unroll
                for (int p = 0; p < 2; ++p) {
                    mma16816(a00 + (2 * p) * 4,     ah[0], bh[p][0], bh[p][1]);
                    mma16816(a10 + (2 * p) * 4,     ah[1], bh[p][0], bh[p][1]);
                    mma16816(a00 + (2 * p + 1) * 4, ah[0], bh[p][2], bh[p][3]);
                    mma16816(a10 + (2 * p + 1) * 4, ah[1], bh[p][2], bh[p][3]);
                }
            }
        }
    }

    // ================= inter-layer epilogue: bias1 + (LN1) + ReLU -> A2 smem =================
#pragma unroll
    for (int nf = 0; nf < 8; ++nf) {
        const int cb = wn * 64 + nf * 8 + gc2v;
        const float b0 = bias1S[cb], b1 = bias1S[cb + 1];
#pragma unroll
        for (int mf = 0; mf < 2; ++mf) {
            acc[mf][nf][0] += b0; acc[mf][nf][1] += b1;
            acc[mf][nf][2] += b0; acc[mf][nf][3] += b1;
        }
    }
    float mean_[2][2], rs_[2][2];
    if (path == 0) {
        float s1[2][2] = {{0.f,0.f},{0.f,0.f}}, s2[2][2] = {{0.f,0.f},{0.f,0.f}};
#pragma unroll
        for (int nf = 0; nf < 8; ++nf)
#pragma unroll
            for (int mf = 0; mf < 2; ++mf) {
                s1[mf][0] += acc[mf][nf][0] + acc[mf][nf][1];
                s2[mf][0] += acc[mf][nf][0]*acc[mf][nf][0] + acc[mf][nf][1]*acc[mf][nf][1];
                s1[mf][1] += acc[mf][nf][2] + acc[mf][nf][3];
                s2[mf][1] += acc[mf][nf][2]*acc[mf][nf][2] + acc[mf][nf][3]*acc[mf][nf][3];
            }
#pragma unroll
        for (int mf = 0; mf < 2; ++mf)
#pragma unroll
            for (int h = 0; h < 2; ++h) {
                s1[mf][h] += __shfl_xor_sync(0xffffffffu, s1[mf][h], 1);
                s1[mf][h] += __shfl_xor_sync(0xffffffffu, s1[mf][h], 2);
                s2[mf][h] += __shfl_xor_sync(0xffffffffu, s2[mf][h], 1);
                s2[mf][h] += __shfl_xor_sync(0xffffffffu, s2[mf][h], 2);
            }
        if ((lane & 3) == 0) {
#pragma unroll
            for (int mf = 0; mf < 2; ++mf)
#pragma unroll
                for (int h = 0; h < 2; ++h) {
                    const int row = wm * 32 + mf * 16 + h * 8 + gr;
                    s1buf[wn * 64 + row] = s1[mf][h];
                    s2buf[wn * 64 + row] = s2[mf][h];
                }
        }
        __syncthreads();
#pragma unroll
        for (int mf = 0; mf < 2; ++mf)
#pragma unroll
            for (int h = 0; h < 2; ++h) {
                const int row = wm * 32 + mf * 16 + h * 8 + gr;
                const float t1 = s1buf[row] + s1buf[64 + row] + s1buf[128 + row] + s1buf[192 + row];
                const float t2 = s2buf[row] + s2buf[64 + row] + s2buf[128 + row] + s2buf[192 + row];
                const float mean = t1 * (1.0f / 256.0f);
                const float var  = t2 * (1.0f / 256.0f) - mean * mean;
                mean_[mf][h] = mean;
                rs_[mf][h]   = rsqrtf(var + 1e-5f);
            }
    }
    {
        char* A2 = smem + OFF_A2;
#pragma unroll
        for (int nf = 0; nf < 8; ++nf) {
            const int cb = wn * 64 + nf * 8 + gc2v;
            float g0 = 1.f, g1 = 1.f, be0 = 0.f, be1 = 0.f;
            if (path == 0) { g0 = gamma1S[cb]; g1 = gamma1S[cb + 1]; be0 = beta1S[cb]; be1 = beta1S[cb + 1]; }
#pragma unroll
            for (int mf = 0; mf < 2; ++mf) {
                float y[4];
                if (path == 0) {
                    y[0] = (acc[mf][nf][0] - mean_[mf][0]) * rs_[mf][0] * g0 + be0;
                    y[1] = (acc[mf][nf][1] - mean_[mf][0]) * rs_[mf][0] * g1 + be1;
                    y[2] = (acc[mf][nf][2] - mean_[mf][1]) * rs_[mf][1] * g0 + be0;
                    y[3] = (acc[mf][nf][3] - mean_[mf][1]) * rs_[mf][1] * g1 + be1;
                } else {
                    y[0] = acc[mf][nf][0]; y[1] = acc[mf][nf][1];
                    y[2] = acc[mf][nf][2]; y[3] = acc[mf][nf][3];
                }
#pragma unroll
                for (int i = 0; i < 4; ++i) y[i] = fmaxf(y[i], 0.f);
                const int r0 = wm * 32 + mf * 16 + gr;
                *(uint32_t*)(A2 + r0 * LDA2 + cb * 2)       = pack2_f16(y[0], y[1]);
                *(uint32_t*)(A2 + (r0 + 8) * LDA2 + cb * 2) = pack2_f16(y[2], y[3]);
            }
        }
    }
    // zero accumulators for layer 2
#pragma unroll
    for (int mf = 0; mf < 2; ++mf)
#pragma unroll
        for (int nf = 0; nf < 8; ++nf)
#pragma unroll
            for (int i = 0; i < 4; ++i) acc[mf][nf][i] = 0.f;

    // ================= mainloop 2 (layer 2; A from smem A2) =================
#pragma unroll 1
    for (int kt = 0; kt < 8; ++kt) {
        const int g = 8 + kt;
        CP_WAIT(0);
        __syncthreads();                 // B2 chunk g visible; A2 writes visible (kt==0); prev consumed
        if (kt < 7) { load_g(g + 1, (g + 1) & 1); CP_COMMIT(); }
        const uint32_t baseB = bufs_s + (g & 1) * BUF_BYTES + A_COMP;
#pragma unroll
        for (int ks = 0; ks < 2; ++ks) {
            const uint32_t kb = ks * 32;
            const uint32_t k16off = (uint32_t)(kt * 2 + ks) * 32;
            uint32_t ah[2][4];
            LDSM4(ah[0], a2_off + k16off);
            LDSM4(ah[1], a2_off + 16 * LDA2 + k16off);
#pragma unroll
            for (int np2 = 0; np2 < 2; ++np2) {
                uint32_t bh[2][4];
#pragma unroll
                for (int p = 0; p < 2; ++p)
                    LDSM4(bh[p], baseB + b_off + (np2 * 2 + p) * (16 * LDA) + kb);
                float* a00 = acc[0][4 * np2];
                float* a10 = acc[1][4 * np2];
#pragma unroll
                for (int p = 0; p < 2; ++p) {
                    mma16816(a00 + (2 * p) * 4,     ah[0], bh[p][0], bh[p][1]);
                    mma16816(a10 + (2 * p) * 4,     ah[1], bh[p][0], bh[p][1]);
                    mma16816(a00 + (2 * p + 1) * 4, ah[0], bh[p][2], bh[p][3]);
                    mma16816(a10 + (2 * p + 1) * 4, ah[1], bh[p][2], bh[p][3]);
                }
            }
        }
    }
    __syncthreads();   // buffers dead; psum (aliased) may now be written

    // ================= final epilogue: bias2 + (LN2) + ReLU + head =================
#pragma unroll
    for (int nf = 0; nf < 8; ++nf) {
        const int cb = wn * 64 + nf * 8 + gc2v;
        const float b0 = bias2S[cb], b1 = bias2S[cb + 1];
#pragma unroll
        for (int mf = 0; mf < 2; ++mf) {
            acc[mf][nf][0] += b0; acc[mf][nf][1] += b1;
            acc[mf][nf][2] += b0; acc[mf][nf][3] += b1;
        }
    }
    if (path == 0) {
        float s1[2][2] = {{0.f,0.f},{0.f,0.f}}, s2[2][2] = {{0.f,0.f},{0.f,0.f}};
#pragma unroll
        for (int nf = 0; nf < 8; ++nf)
#pragma unroll
            for (int mf = 0; mf < 2; ++mf) {
                s1[mf][0] += acc[mf][nf][0] + acc[mf][nf][1];
                s2[mf][0] += acc[mf][nf][0]*acc[mf][nf][0] + acc[mf][nf][1]*acc[mf][nf][1];
                s1[mf][1] += acc[mf][nf][2] + acc[mf][nf][3];
                s2[mf][1] += acc[mf][nf][2]*acc[mf][nf][2] + acc[mf][nf][3]*acc[mf][nf][3];
            }
#pragma unroll
        for (int mf = 0; mf < 2; ++mf)
#pragma unroll
            for (int h = 0; h < 2; ++h) {
                s1[mf][h] += __shfl_xor_sync(0xffffffffu, s1[mf][h], 1);
                s1[mf][h] += __shfl_xor_sync(0xffffffffu, s1[mf][h], 2);
                s2[mf][h] += __shfl_xor_sync(0xffffffffu, s2[mf][h], 1);
                s2[mf][h] += __shfl_xor_sync(0xffffffffu, s2[mf][h], 2);
            }
        if ((lane & 3) == 0) {
#pragma unroll
            for (int mf = 0; mf < 2; ++mf)
#pragma unroll
                for (int h = 0; h < 2; ++h) {
                    const int row = wm * 32 + mf * 16 + h * 8 + gr;
                    s1buf[wn * 64 + row] = s1[mf][h];
                    s2buf[wn * 64 + row] = s2[mf][h];
                }
        }
        __syncthreads();
#pragma unroll
        for (int mf = 0; mf < 2; ++mf)
#pragma unroll
            for (int h = 0; h < 2; ++h) {
                const int row = wm * 32 + mf * 16 + h * 8 + gr;
                const float t1 = s1buf[row] + s1buf[64 + row] + s1buf[128 + row] + s1buf[192 + row];
                const float t2 = s2buf[row] + s2buf[64 + row] + s2buf[128 + row] + s2buf[192 + row];
                const float mean = t1 * (1.0f / 256.0f);
                const float var  = t2 * (1.0f / 256.0f) - mean * mean;
                mean_[mf][h] = mean;
                rs_[mf][h]   = rsqrtf(var + 1e-5f);
            }
    }

    // fused head: y -> 10-dim GEMV partials, reduce, coord transform
    float part[4][10];
#pragma unroll
    for (int s = 0; s < 4; ++s)
#pragma unroll
        for (int nc = 0; nc < 10; ++nc) part[s][nc] = 0.f;

#pragma unroll
    for (int nf = 0; nf < 8; ++nf) {
        const int cb = wn * 64 + nf * 8 + gc2v;
        float g0 = 1.f, g1 = 1.f, be0 = 0.f, be1 = 0.f;
        if (path == 0) { g0 = gamma2S[cb]; g1 = gamma2S[cb + 1]; be0 = beta2S[cb]; be1 = beta2S[cb + 1]; }
        float y[2][4];
#pragma unroll
        for (int mf = 0; mf < 2; ++mf) {
            if (path == 0) {
                y[mf][0] = (acc[mf][nf][0] - mean_[mf][0]) * rs_[mf][0] * g0 + be0;
                y[mf][1] = (acc[mf][nf][1] - mean_[mf][0]) * rs_[mf][0] * g1 + be1;
                y[mf][2] = (acc[mf][nf][2] - mean_[mf][1]) * rs_[mf][1] * g0 + be0;
                y[mf][3] = (acc[mf][nf][3] - mean_[mf][1]) * rs_[mf][1] * g1 + be1;
            } else {
                y[mf][0] = acc[mf][nf][0]; y[mf][1] = acc[mf][nf][1];
                y[mf][2] = acc[mf][nf][2]; y[mf][3] = acc[mf][nf][3];
            }
#pragma unroll
            for (int i = 0; i < 4; ++i) y[mf][i] = fmaxf(y[mf][i], 0.f);
        }
        const float* w0 = &W3s[cb * 12];
        const float* w1 = &W3s[(cb + 1) * 12];
#pragma unroll
        for (int nc = 0; nc < 10; ++nc) {
            const float a0 = w0[nc], a1 = w1[nc];
#pragma unroll
            for (int mf = 0; mf < 2; ++mf) {
                part[mf * 2 + 0][nc] = fmaf(y[mf][0], a0, fmaf(y[mf][1], a1, part[mf * 2 + 0][nc]));
                part[mf * 2 + 1][nc] = fmaf(y[mf][2], a0, fmaf(y[mf][3], a1, part[mf * 2 + 1][nc]));
            }
        }
    }
#pragma unroll
    for (int s = 0; s < 4; ++s)
#pragma unroll
        for (int nc = 0; nc < 10; ++nc) {
            part[s][nc] += __shfl_xor_sync(0xffffffffu, part[s][nc], 1);
            part[s][nc] += __shfl_xor_sync(0xffffffffu, part[s][nc], 2);
        }
    if ((lane & 3) == 0) {
#pragma unroll
        for (int mf = 0; mf < 2; ++mf)
#pragma unroll
            for (int h = 0; h < 2; ++h) {
                const int row = wm * 32 + mf * 16 + h * 8 + gr;
                float* p = &psum[((size_t)wn * 64 + row) * 12];
#pragma unroll
                for (int nc = 0; nc < 10; ++nc) p[nc] = part[mf * 2 + h][nc];
            }
    }
    __syncthreads();

    if (t < 64) {
        const int row = t;
        const int m = m0 + row;
        const int q = m >> 5, b = m & 31;
        const size_t base = (((size_t)l * BB + b) * QQ + q) * 10;
        float val[10];
        const float* b3 = (path ? rb3 : cb3) + l * 10;
#pragma unroll
        for (int nc = 0; nc < 10; ++nc)
            val[nc] = psum[row * 12 + nc] + psum[(64 + row) * 12 + nc]
                    + psum[(128 + row) * 12 + nc] + psum[(192 + row) * 12 + nc] + b3[nc];
        if (path == 0) {
#pragma unroll
            for (int nc = 0; nc < 10; ++nc) out[base + nc] = val[nc];   // cls scores
        } else {
            const float* rp = (l == 0)
                ? (init_ref + ((size_t)b * QQ + q) * 3)
                : (inter_ref + (((size_t)(l - 1) * BB + b) * QQ + q) * 3);
            float r[3];
#pragma unroll
            for (int i = 0; i < 3; ++i) {
                const float x  = fminf(fmaxf(rp[i], 0.f), 1.f);
                const float x1 = fmaxf(x, 1e-5f);
                const float x2 = fmaxf(1.f - x, 1e-5f);
                r[i] = logf(x1 / x2);
            }
            const float xy0 = 1.f / (1.f + expf(-(val[0] + r[0])));
            const float xy1 = 1.f / (1.f + expf(-(val[1] + r[1])));
            const float z   = 1.f / (1.f + expf(-(val[4] + r[2])));
            float* co = out + (size_t)L6 * BB * QQ * 10 + base;
            co[0] = xy0 * 102.4f - 51.2f;
            co[1] = xy1 * 102.4f - 51.2f;
            co[2] = val[2];
            co[3] = val[3];
            co[4] = z * 8.0f - 5.0f;
            co[5] = val[5]; co[6] = val[6]; co[7] = val[7]; co[8] = val[8]; co[9] = val[9];
        }
    }
}

extern "C" void kernel_launch(void* const* d_in, const int* in_sizes, int n_in,
                              void* d_out, int out_size) {
    const float* hs        = (const float*)d_in[0];
    const float* init_ref  = (const float*)d_in[1];
    const float* inter_ref = (const float*)d_in[2];
    const float* cls_w1    = (const float*)d_in[3];
    const float* cls_b1    = (const float*)d_in[4];
    const float* ln1_g     = (const float*)d_in[5];
    const float* ln1_b     = (const float*)d_in[6];
    const float* cls_w2    = (const float*)d_in[7];
    const float* cls_b2    = (const float*)d_in[8];
    const float* ln2_g     = (const float*)d_in[9];
    const float* ln2_b     = (const float*)d_in[10];
    const float* cls_w3    = (const float*)d_in[11];
    const float* cls_b3    = (const float*)d_in[12];
    const float* reg_w1    = (const float*)d_in[13];
    const float* reg_b1    = (const float*)d_in[14];
    const float* reg_w2    = (const float*)d_in[15];
    const float* reg_b2    = (const float*)d_in[16];
    const float* reg_w3    = (const float*)d_in[17];
    const float* reg_b3    = (const float*)d_in[18];
    float* out = (float*)d_out;

    cudaFuncSetAttribute(fused_mlp_kernel, cudaFuncAttributeMaxDynamicSharedMemorySize, SMEM_TOTAL);

    split_hs_kernel<<<(int)((size_t)L6 * MM * DD / 4 / 512), 512>>>(hs);
    transpose_weights_kernel<<<dim3(8, 8, 4 * L6), dim3(32, 32)>>>(cls_w1, reg_w1, cls_w2, reg_w2);

    dim3 grid(MM / 64, 2, L6);   // 450 x {cls,reg} x 6
    fused_mlp_kernel<<<grid, 256, SMEM_TOTAL>>>(cls_b1, ln1_g, ln1_b, reg_b1,
                                                cls_b2, ln2_g, ln2_b, reg_b2,
                                                cls_w3, cls_b3, reg_w3, reg_b3,
                                                init_ref, inter_ref, out);
}

// round 14
// speedup vs baseline: 2.5779x; 1.1035x over previous
#include <cuda_runtime.h>
#include <cuda_fp16.h>
#include <math.h>
#include <stdint.h>

#define L6 6
#define BB 32
#define QQ 900
#define DD 256
#define MM (BB*QQ)                 // 28800 tokens per level
#define MD ((size_t)MM*(size_t)DD)

// ---------------- scratch (device globals; allocation-free) ----------------
// transposed weights fp16: [widx][L][N=256][K=256]; widx: 0=cls_w1 1=reg_w1 2=cls_w2 3=reg_w2
__device__ __half g_wb[(size_t)4*L6*DD*DD];

// ---------------- helpers ----------------
__device__ __forceinline__ uint32_t smem_u32(const void* p) {
    uint32_t a;
    asm("{ .reg .u64 t; cvta.to.shared.u64 t, %1; cvt.u32.u64 %0, t; }" : "=r"(a) : "l"(p));
    return a;
}
#define CP_ASYNC16(dst, src) \
    asm volatile("cp.async.cg.shared.global [%0], [%1], 16;" :: "r"(dst), "l"(src))
#define CP_COMMIT() asm volatile("cp.async.commit_group;" ::: "memory")
#define CP_WAIT(n)  asm volatile("cp.async.wait_group %0;" :: "n"(n) : "memory")

#define LDSM4(r, addr) \
    asm volatile("ldmatrix.sync.aligned.m8n8.x4.shared.b16 {%0,%1,%2,%3}, [%4];" \
        : "=r"((r)[0]), "=r"((r)[1]), "=r"((r)[2]), "=r"((r)[3]) : "r"(addr))

__device__ __forceinline__ uint32_t pack2_f16(float x, float y) {
    __half2 h = __halves2half2(__float2half(x), __float2half(y));
    return *reinterpret_cast<uint32_t*>(&h);
}

__device__ __forceinline__ void mma16816(float* c, const uint32_t a[4],
                                         uint32_t b0, uint32_t b1) {
    asm volatile(
        "mma.sync.aligned.m16n8k16.row.col.f32.f16.f16.f32 "
        "{%0,%1,%2,%3}, {%4,%5,%6,%7}, {%8,%9}, {%0,%1,%2,%3};"
        : "+f"(c[0]), "+f"(c[1]), "+f"(c[2]), "+f"(c[3])
        : "r"(a[0]), "r"(a[1]), "r"(a[2]), "r"(a[3]), "r"(b0), "r"(b1));
}

// ---------------- weight transpose + fp16 round ----------------
__global__ void transpose_weights_kernel(const float* __restrict__ w0, const float* __restrict__ w1,
                                         const float* __restrict__ w2, const float* __restrict__ w3)
{
    __shared__ float sT[32][33];
    const float* srcs[4] = {w0, w1, w2, w3};
    const int z = blockIdx.z;
    const int mat = z / L6, l = z - mat * L6;
    const int k0 = blockIdx.y * 32, n0 = blockIdx.x * 32;
    const float* W = srcs[mat] + (size_t)l * DD * DD;   // [K,N] row-major
    sT[threadIdx.y][threadIdx.x] = W[(size_t)(k0 + threadIdx.y) * DD + n0 + threadIdx.x];
    __syncthreads();
    float v = sT[threadIdx.x][threadIdx.y];             // = W[k0+tx][n0+ty]
    size_t o = (((size_t)mat * L6 + l) * DD + (n0 + threadIdx.y)) * DD + k0 + threadIdx.x;
    g_wb[o] = __float2half(v);
}

// ---------------- fused 2-layer HMMA kernel (M=64 tile, 256 thr, 2 CTAs/SM) ----------------
// A converted fp32->fp16 in-kernel into a persistent smem buffer (no gmem pre-pass).
// The same buffer is reused for the layer-2 activations (A2) after mainloop 1.
#define LDA 80
#define B_COMP 20480                // 256 rows * 80 B (one B chunk)
#define BUF_BYTES B_COMP
#define LDA2 528                    // A row stride (256 halfs + 8-half pad)

#define OFF_BIAS1  0
#define OFF_GAMMA1 1024
#define OFF_BETA1  2048
#define OFF_BIAS2  3072
#define OFF_GAMMA2 4096
#define OFF_BETA2  5120
#define OFF_S1     6144
#define OFF_S2     7168
#define OFF_W3     8192      // 256*12*4 = 12288 -> ends 20480
#define OFF_A      20480     // 64*528 = 33792 -> ends 54272 (A1, later A2)
#define OFF_BUFS   54272     // 2*20480 -> ends 95232
#define SMEM_TOTAL 95232
// psum [4][64][12] (12288 B) aliases OFF_BUFS (buffers dead by final epilogue)

__global__ __launch_bounds__(256, 2)
void fused_mlp_kernel(const float* __restrict__ hs,
                      const float* __restrict__ bc1, const float* __restrict__ gc1,
                      const float* __restrict__ bec1, const float* __restrict__ br1,
                      const float* __restrict__ bc2, const float* __restrict__ gc2,
                      const float* __restrict__ bec2, const float* __restrict__ br2,
                      const float* __restrict__ cw3, const float* __restrict__ cb3,
                      const float* __restrict__ rw3, const float* __restrict__ rb3,
                      const float* __restrict__ init_ref, const float* __restrict__ inter_ref,
                      float* __restrict__ out)
{
    extern __shared__ char smem[];
    float* bias1S  = (float*)(smem + OFF_BIAS1);
    float* gamma1S = (float*)(smem + OFF_GAMMA1);
    float* beta1S  = (float*)(smem + OFF_BETA1);
    float* bias2S  = (float*)(smem + OFF_BIAS2);
    float* gamma2S = (float*)(smem + OFF_GAMMA2);
    float* beta2S  = (float*)(smem + OFF_BETA2);
    float* s1buf   = (float*)(smem + OFF_S1);
    float* s2buf   = (float*)(smem + OFF_S2);
    float* W3s     = (float*)(smem + OFF_W3);    // [256][12]
    char*  Abuf    = smem + OFF_A;               // A1, then A2
    float* psum    = (float*)(smem + OFF_BUFS);  // aliased over B buffers
    const uint32_t sb = smem_u32(smem);
    const uint32_t bufs_s = sb + OFF_BUFS;

    const int t = threadIdx.x, lane = t & 31, wid = t >> 5;
    const int wm = wid & 1, wn = wid >> 1;       // warp tile: 32 rows x 64 cols
    const int l = blockIdx.z, path = blockIdx.y, m0 = blockIdx.x * 64;

    const __half* W1g = g_wb + ((size_t)(0 * 2 + path) * L6 + l) * DD * DD;
    const __half* W2g = g_wb + ((size_t)(1 * 2 + path) * L6 + l) * DD * DD;
    const float*  Ag  = hs + (size_t)l * MD + (size_t)m0 * DD;   // fp32, [64,256] tile

    // ---- B chunk loader: g in 0..15; g<8: W1 chunk g; g>=8: W2 chunk g-8 ----
    auto load_g = [&](int g, int buf) {
        const uint32_t base = bufs_s + buf * BUF_BYTES;
        const __half* Wsrc = (g < 8) ? W1g : W2g;
        const int kc = (g & 7) * 32;
#pragma unroll
        for (int s = 0; s < 4; ++s) {
            const int idx = s * 256 + t, r = idx >> 2, cc = idx & 3;
            CP_ASYNC16(base + r * LDA + cc * 16, Wsrc + (size_t)r * DD + kc + cc * 8);
        }
    };

    load_g(0, 0); CP_COMMIT();

    // ---- A conversion: 64x256 fp32 -> fp16 into Abuf (overlaps chunk-0 cp.async) ----
#pragma unroll
    for (int s = 0; s < 16; ++s) {
        const int idx = s * 256 + t;
        const int row = idx >> 6, c4 = idx & 63;        // 64 float4s per row
        const float4 f = *(const float4*)(Ag + (size_t)row * DD + c4 * 4);
        *(uint2*)(Abuf + row * LDA2 + c4 * 8) =
            make_uint2(pack2_f16(f.x, f.y), pack2_f16(f.z, f.w));
    }

    // ---- parameter loads ----
    bias1S[t] = ((path ? br1 : bc1) + l * DD)[t];
    bias2S[t] = ((path ? br2 : bc2) + l * DD)[t];
    if (path == 0) {
        gamma1S[t] = gc1[l * DD + t]; beta1S[t] = bec1[l * DD + t];
        gamma2S[t] = gc2[l * DD + t]; beta2S[t] = bec2[l * DD + t];
    }
    {
        const float* w3g = (path ? rw3 : cw3) + l * 2560;
        for (int idx = t; idx < 2560; idx += 256) {
            const int k = idx / 10, nc = idx - k * 10;
            W3s[k * 12 + nc] = w3g[idx];
        }
    }

    float acc[2][8][4];
#pragma unroll
    for (int mf = 0; mf < 2; ++mf)
#pragma unroll
        for (int nf = 0; nf < 8; ++nf)
#pragma unroll
            for (int i = 0; i < 4; ++i) acc[mf][nf][i] = 0.f;

    const int gr = lane >> 2, gc2v = (lane & 3) << 1;
    const uint32_t b_off = (uint32_t)(wn * 64 + (lane & 7) + ((lane >> 4) & 1) * 8) * LDA
                         + ((lane >> 3) & 1) * 16;
    const uint32_t a_off = sb + OFF_A
                         + (uint32_t)(wm * 32 + (lane & 7) + ((lane >> 3) & 1) * 8) * LDA2
                         + ((lane >> 4) & 1) * 16;

    // ================= mainloop 1 (layer 1; A from smem, B double-buffered) =================
#pragma unroll 1
    for (int kt = 0; kt < 8; ++kt) {
        CP_WAIT(0);
        __syncthreads();                 // chunk kt + A conversion visible; kt-1 consumed
        load_g(kt + 1, (kt + 1) & 1);    // kt+1 <= 8 (g=8 -> W2 chunk 0)
        CP_COMMIT();
        const uint32_t baseB = bufs_s + (kt & 1) * BUF_BYTES;
#pragma unroll
        for (int ks = 0; ks < 2; ++ks) {
            const uint32_t kb = ks * 32;
            const uint32_t k16off = (uint32_t)(kt * 2 + ks) * 32;
            uint32_t ah[2][4];
            LDSM4(ah[0], a_off + k16off);
            LDSM4(ah[1], a_off + 16 * LDA2 + k16off);
#pragma unroll
            for (int np2 = 0; np2 < 2; ++np2) {
                uint32_t bh[2][4];
#pragma unroll
                for (int p = 0; p < 2; ++p)
                    LDSM4(bh[p], baseB + b_off + (np2 * 2 + p) * (16 * LDA) + kb);
                float* a00 = acc[0][4 * np2];
                float* a10 = acc[1][4 * np2];
#pragma unroll
                for (int p = 0; p < 2; ++p) {
                    mma16816(a00 + (2 * p) * 4,     ah[0], bh[p][0], bh[p][1]);
                    mma16816(a10 + (2 * p) * 4,     ah[1], bh[p][0], bh[p][1]);
                    mma16816(a00 + (2 * p + 1) * 4, ah[0], bh[p][2], bh[p][3]);
                    mma16816(a10 + (2 * p + 1) * 4, ah[1], bh[p][2], bh[p][3]);
                }
            }
        }
    }
    __syncthreads();   // all warps done reading A1; safe to overwrite Abuf with A2

    // ================= inter-layer epilogue: bias1 + (LN1) + ReLU -> Abuf (A2) =================
#pragma unroll
    for (int nf = 0; nf < 8; ++nf) {
        const int cb = wn * 64 + nf * 8 + gc2v;
        const float b0 = bias1S[cb], b1 = bias1S[cb + 1];
#pragma unroll
        for (int mf = 0; mf < 2; ++mf) {
            acc[mf][nf][0] += b0; acc[mf][nf][1] += b1;
            acc[mf][nf][2] += b0; acc[mf][nf][3] += b1;
        }
    }
    float mean_[2][2], rs_[2][2];
    if (path == 0) {
        float s1[2][2] = {{0.f,0.f},{0.f,0.f}}, s2[2][2] = {{0.f,0.f},{0.f,0.f}};
#pragma unroll
        for (int nf = 0; nf < 8; ++nf)
#pragma unroll
            for (int mf = 0; mf < 2; ++mf) {
                s1[mf][0] += acc[mf][nf][0] + acc[mf][nf][1];
                s2[mf][0] += acc[mf][nf][0]*acc[mf][nf][0] + acc[mf][nf][1]*acc[mf][nf][1];
                s1[mf][1] += acc[mf][nf][2] + acc[mf][nf][3];
                s2[mf][1] += acc[mf][nf][2]*acc[mf][nf][2] + acc[mf][nf][3]*acc[mf][nf][3];
            }
#pragma unroll
        for (int mf = 0; mf < 2; ++mf)
#pragma unroll
            for (int h = 0; h < 2; ++h) {
                s1[mf][h] += __shfl_xor_sync(0xffffffffu, s1[mf][h], 1);
                s1[mf][h] += __shfl_xor_sync(0xffffffffu, s1[mf][h], 2);
                s2[mf][h] += __shfl_xor_sync(0xffffffffu, s2[mf][h], 1);
                s2[mf][h] += __shfl_xor_sync(0xffffffffu, s2[mf][h], 2);
            }
        if ((lane & 3) == 0) {
#pragma unroll
            for (int mf = 0; mf < 2; ++mf)
#pragma unroll
                for (int h = 0; h < 2; ++h) {
                    const int row = wm * 32 + mf * 16 + h * 8 + gr;
                    s1buf[wn * 64 + row] = s1[mf][h];
                    s2buf[wn * 64 + row] = s2[mf][h];
                }
        }
        __syncthreads();
#pragma unroll
        for (int mf = 0; mf < 2; ++mf)
#pragma unroll
            for (int h = 0; h < 2; ++h) {
                const int row = wm * 32 + mf * 16 + h * 8 + gr;
                const float t1 = s1buf[row] + s1buf[64 + row] + s1buf[128 + row] + s1buf[192 + row];
                const float t2 = s2buf[row] + s2buf[64 + row] + s2buf[128 + row] + s2buf[192 + row];
                const float mean = t1 * (1.0f / 256.0f);
                const float var  = t2 * (1.0f / 256.0f) - mean * mean;
                mean_[mf][h] = mean;
                rs_[mf][h]   = rsqrtf(var + 1e-5f);
            }
    }
    {
#pragma unroll
        for (int nf = 0; nf < 8; ++nf) {
            const int cb = wn * 64 + nf * 8 + gc2v;
            float g0 = 1.f, g1 = 1.f, be0 = 0.f, be1 = 0.f;
            if (path == 0) { g0 = gamma1S[cb]; g1 = gamma1S[cb + 1]; be0 = beta1S[cb]; be1 = beta1S[cb + 1]; }
#pragma unroll
            for (int mf = 0; mf < 2; ++mf) {
                float y[4];
                if (path == 0) {
                    y[0] = (acc[mf][nf][0] - mean_[mf][0]) * rs_[mf][0] * g0 + be0;
                    y[1] = (acc[mf][nf][1] - mean_[mf][0]) * rs_[mf][0] * g1 + be1;
                    y[2] = (acc[mf][nf][2] - mean_[mf][1]) * rs_[mf][1] * g0 + be0;
                    y[3] = (acc[mf][nf][3] - mean_[mf][1]) * rs_[mf][1] * g1 + be1;
                } else {
                    y[0] = acc[mf][nf][0]; y[1] = acc[mf][nf][1];
                    y[2] = acc[mf][nf][2]; y[3] = acc[mf][nf][3];
                }
#pragma unroll
                for (int i = 0; i < 4; ++i) y[i] = fmaxf(y[i], 0.f);
                const int r0 = wm * 32 + mf * 16 + gr;
                *(uint32_t*)(Abuf + r0 * LDA2 + cb * 2)       = pack2_f16(y[0], y[1]);
                *(uint32_t*)(Abuf + (r0 + 8) * LDA2 + cb * 2) = pack2_f16(y[2], y[3]);
            }
        }
    }
    // zero accumulators for layer 2
#pragma unroll
    for (int mf = 0; mf < 2; ++mf)
#pragma unroll
        for (int nf = 0; nf < 8; ++nf)
#pragma unroll
            for (int i = 0; i < 4; ++i) acc[mf][nf][i] = 0.f;

    // ================= mainloop 2 (layer 2; A from smem A2) =================
#pragma unroll 1
    for (int kt = 0; kt < 8; ++kt) {
        const int g = 8 + kt;
        CP_WAIT(0);
        __syncthreads();                 // B2 chunk g visible; A2 writes visible (kt==0)
        if (kt < 7) { load_g(g + 1, (g + 1) & 1); CP_COMMIT(); }
        const uint32_t baseB = bufs_s + (g & 1) * BUF_BYTES;
#pragma unroll
        for (int ks = 0; ks < 2; ++ks) {
            const uint32_t kb = ks * 32;
            const uint32_t k16off = (uint32_t)(kt * 2 + ks) * 32;
            uint32_t ah[2][4];
            LDSM4(ah[0], a_off + k16off);
            LDSM4(ah[1], a_off + 16 * LDA2 + k16off);
#pragma unroll
            for (int np2 = 0; np2 < 2; ++np2) {
                uint32_t bh[2][4];
#pragma unroll
                for (int p = 0; p < 2; ++p)
                    LDSM4(bh[p], baseB + b_off + (np2 * 2 + p) * (16 * LDA) + kb);
                float* a00 = acc[0][4 * np2];
                float* a10 = acc[1][4 * np2];
#pragma unroll
                for (int p = 0; p < 2; ++p) {
                    mma16816(a00 + (2 * p) * 4,     ah[0], bh[p][0], bh[p][1]);
                    mma16816(a10 + (2 * p) * 4,     ah[1], bh[p][0], bh[p][1]);
                    mma16816(a00 + (2 * p + 1) * 4, ah[0], bh[p][2], bh[p][3]);
                    mma16816(a10 + (2 * p + 1) * 4, ah[1], bh[p][2], bh[p][3]);
                }
            }
        }
    }
    __syncthreads();   // buffers dead; psum (aliased) may now be written

    // ================= final epilogue: bias2 + (LN2) + ReLU + head =================
#pragma unroll
    for (int nf = 0; nf < 8; ++nf) {
        const int cb = wn * 64 + nf * 8 + gc2v;
        const float b0 = bias2S[cb], b1 = bias2S[cb + 1];
#pragma unroll
        for (int mf = 0; mf < 2; ++mf) {
            acc[mf][nf][0] += b0; acc[mf][nf][1] += b1;
            acc[mf][nf][2] += b0; acc[mf][nf][3] += b1;
        }
    }
    if (path == 0) {
        float s1[2][2] = {{0.f,0.f},{0.f,0.f}}, s2[2][2] = {{0.f,0.f},{0.f,0.f}};
#pragma unroll
        for (int nf = 0; nf < 8; ++nf)
#pragma unroll
            for (int mf = 0; mf < 2; ++mf) {
                s1[mf][0] += acc[mf][nf][0] + acc[mf][nf][1];
                s2[mf][0] += acc[mf][nf][0]*acc[mf][nf][0] + acc[mf][nf][1]*acc[mf][nf][1];
                s1[mf][1] += acc[mf][nf][2] + acc[mf][nf][3];
                s2[mf][1] += acc[mf][nf][2]*acc[mf][nf][2] + acc[mf][nf][3]*acc[mf][nf][3];
            }
#pragma unroll
        for (int mf = 0; mf < 2; ++mf)
#pragma unroll
            for (int h = 0; h < 2; ++h) {
                s1[mf][h] += __shfl_xor_sync(0xffffffffu, s1[mf][h], 1);
                s1[mf][h] += __shfl_xor_sync(0xffffffffu, s1[mf][h], 2);
                s2[mf][h] += __shfl_xor_sync(0xffffffffu, s2[mf][h], 1);
                s2[mf][h] += __shfl_xor_sync(0xffffffffu, s2[mf][h], 2);
            }
        if ((lane & 3) == 0) {
#pragma unroll
            for (int mf = 0; mf < 2; ++mf)
#pragma unroll
                for (int h = 0; h < 2; ++h) {
                    const int row = wm * 32 + mf * 16 + h * 8 + gr;
                    s1buf[wn * 64 + row] = s1[mf][h];
                    s2buf[wn * 64 + row] = s2[mf][h];
                }
        }
        __syncthreads();
#pragma unroll
        for (int mf = 0; mf < 2; ++mf)
#pragma unroll
            for (int h = 0; h < 2; ++h) {
                const int row = wm * 32 + mf * 16 + h * 8 + gr;
                const float t1 = s1buf[row] + s1buf[64 + row] + s1buf[128 + row] + s1buf[192 + row];
                const float t2 = s2buf[row] + s2buf[64 + row] + s2buf[128 + row] + s2buf[192 + row];
                const float mean = t1 * (1.0f / 256.0f);
                const float var  = t2 * (1.0f / 256.0f) - mean * mean;
                mean_[mf][h] = mean;
                rs_[mf][h]   = rsqrtf(var + 1e-5f);
            }
    }

    // fused head: y -> 10-dim GEMV partials, reduce, coord transform
    float part[4][10];
#pragma unroll
    for (int s = 0; s < 4; ++s)
#pragma unroll
        for (int nc = 0; nc < 10; ++nc) part[s][nc] = 0.f;

#pragma unroll
    for (int nf = 0; nf < 8; ++nf) {
        const int cb = wn * 64 + nf * 8 + gc2v;
        float g0 = 1.f, g1 = 1.f, be0 = 0.f, be1 = 0.f;
        if (path == 0) { g0 = gamma2S[cb]; g1 = gamma2S[cb + 1]; be0 = beta2S[cb]; be1 = beta2S[cb + 1]; }
        float y[2][4];
#pragma unroll
        for (int mf = 0; mf < 2; ++mf) {
            if (path == 0) {
                y[mf][0] = (acc[mf][nf][0] - mean_[mf][0]) * rs_[mf][0] * g0 + be0;
                y[mf][1] = (acc[mf][nf][1] - mean_[mf][0]) * rs_[mf][0] * g1 + be1;
                y[mf][2] = (acc[mf][nf][2] - mean_[mf][1]) * rs_[mf][1] * g0 + be0;
                y[mf][3] = (acc[mf][nf][3] - mean_[mf][1]) * rs_[mf][1] * g1 + be1;
            } else {
                y[mf][0] = acc[mf][nf][0]; y[mf][1] = acc[mf][nf][1];
                y[mf][2] = acc[mf][nf][2]; y[mf][3] = acc[mf][nf][3];
            }
#pragma unroll
            for (int i = 0; i < 4; ++i) y[mf][i] = fmaxf(y[mf][i], 0.f);
        }
        const float* w0 = &W3s[cb * 12];
        const float* w1 = &W3s[(cb + 1) * 12];
#pragma unroll
        for (int nc = 0; nc < 10; ++nc) {
            const float a0 = w0[nc], a1 = w1[nc];
#pragma unroll
            for (int mf = 0; mf < 2; ++mf) {
                part[mf * 2 + 0][nc] = fmaf(y[mf][0], a0, fmaf(y[mf][1], a1, part[mf * 2 + 0][nc]));
                part[mf * 2 + 1][nc] = fmaf(y[mf][2], a0, fmaf(y[mf][3], a1, part[mf * 2 + 1][nc]));
            }
        }
    }
#pragma unroll
    for (int s = 0; s < 4; ++s)
#pragma unroll
        for (int nc = 0; nc < 10; ++nc) {
            part[s][nc] += __shfl_xor_sync(0xffffffffu, part[s][nc], 1);
            part[s][nc] += __shfl_xor_sync(0xffffffffu, part[s][nc], 2);
        }
    if ((lane & 3) == 0) {
#pragma unroll
        for (int mf = 0; mf < 2; ++mf)
#pragma unroll
            for (int h = 0; h < 2; ++h) {
                const int row = wm * 32 + mf * 16 + h * 8 + gr;
                float* p = &psum[((size_t)wn * 64 + row) * 12];
#pragma unroll
                for (int nc = 0; nc < 10; ++nc) p[nc] = part[mf * 2 + h][nc];
            }
    }
    __syncthreads();

    if (t < 64) {
        const int row = t;
        const int m = m0 + row;
        const int q = m >> 5, b = m & 31;
        const size_t base = (((size_t)l * BB + b) * QQ + q) * 10;
        float val[10];
        const float* b3 = (path ? rb3 : cb3) + l * 10;
#pragma unroll
        for (int nc = 0; nc < 10; ++nc)
            val[nc] = psum[row * 12 + nc] + psum[(64 + row) * 12 + nc]
                    + psum[(128 + row) * 12 + nc] + psum[(192 + row) * 12 + nc] + b3[nc];
        if (path == 0) {
#pragma unroll
            for (int nc = 0; nc < 10; ++nc) out[base + nc] = val[nc];   // cls scores
        } else {
            const float* rp = (l == 0)
                ? (init_ref + ((size_t)b * QQ + q) * 3)
                : (inter_ref + (((size_t)(l - 1) * BB + b) * QQ + q) * 3);
            float r[3];
#pragma unroll
            for (int i = 0; i < 3; ++i) {
                const float x  = fminf(fmaxf(rp[i], 0.f), 1.f);
                const float x1 = fmaxf(x, 1e-5f);
                const float x2 = fmaxf(1.f - x, 1e-5f);
                r[i] = logf(x1 / x2);
            }
            const float xy0 = 1.f / (1.f + expf(-(val[0] + r[0])));
            const float xy1 = 1.f / (1.f + expf(-(val[1] + r[1])));
            const float z   = 1.f / (1.f + expf(-(val[4] + r[2])));
            float* co = out + (size_t)L6 * BB * QQ * 10 + base;
            co[0] = xy0 * 102.4f - 51.2f;
            co[1] = xy1 * 102.4f - 51.2f;
            co[2] = val[2];
            co[3] = val[3];
            co[4] = z * 8.0f - 5.0f;
            co[5] = val[5]; co[6] = val[6]; co[7] = val[7]; co[8] = val[8]; co[9] = val[9];
        }
    }
}

extern "C" void kernel_launch(void* const* d_in, const int* in_sizes, int n_in,
                              void* d_out, int out_size) {
    const float* hs        = (const float*)d_in[0];
    const float* init_ref  = (const float*)d_in[1];
    const float* inter_ref = (const float*)d_in[2];
    const float* cls_w1    = (const float*)d_in[3];
    const float* cls_b1    = (const float*)d_in[4];
    const float* ln1_g     = (const float*)d_in[5];
    const float* ln1_b     = (const float*)d_in[6];
    const float* cls_w2    = (const float*)d_in[7];
    const float* cls_b2    = (const float*)d_in[8];
    const float* ln2_g     = (const float*)d_in[9];
    const float* ln2_b     = (const float*)d_in[10];
    const float* cls_w3    = (const float*)d_in[11];
    const float* cls_b3    = (const float*)d_in[12];
    const float* reg_w1    = (const float*)d_in[13];
    const float* reg_b1    = (const float*)d_in[14];
    const float* reg_w2    = (const float*)d_in[15];
    const float* reg_b2    = (const float*)d_in[16];
    const float* reg_w3    = (const float*)d_in[17];
    const float* reg_b3    = (const float*)d_in[18];
    float* out = (float*)d_out;

    cudaFuncSetAttribute(fused_mlp_kernel, cudaFuncAttributeMaxDynamicSharedMemorySize, SMEM_TOTAL);

    transpose_weights_kernel<<<dim3(8, 8, 4 * L6), dim3(32, 32)>>>(cls_w1, reg_w1, cls_w2, reg_w2);

    dim3 grid(MM / 64, 2, L6);   // 450 x {cls,reg} x 6
    fused_mlp_kernel<<<grid, 256, SMEM_TOTAL>>>(hs,
                                                cls_b1, ln1_g, ln1_b, reg_b1,
                                                cls_b2, ln2_g, ln2_b, reg_b2,
                                                cls_w3, cls_b3, reg_w3, reg_b3,
                                                init_ref, inter_ref, out);
}